// round 14
// baseline (speedup 1.0000x reference)
#include <cuda_runtime.h>
#include <cuda_fp16.h>
#include <math.h>
#include <stdint.h>

#define H       128
#define NNODES  50000
#define NEDGES  600000
#define NTYPES  9

#define SBLK    512
#define NSB     ((NNODES + SBLK - 1) / SBLK)   // 98

#define PITCH   136                 // fp16 units; 272B rows, ldmatrix-friendly
#define MMA_SMEM ((128*PITCH + 128*PITCH) * 2)    // 69632 B -> 3 CTA/SM
#define GGF_SMEM ((128*PITCH + 384*PITCH) * 2)    // 139264 B -> 1 CTA/SM, 512 thr

#define GB_TOT  ((NNODES + 127) / 128)   // 391
#define GB1     196
#define GB2     (GB_TOT - GB1)           // 195
#define NHALF1  (GB1 * 128)              // 25088
#define NHALF2  (NNODES - NHALF1)        // 24912

// ---------------- scratch ----------------
__device__ __half g_hWh[NNODES * H];                  // hW (fp16)
__device__ __half g_gih[NNODES * 3 * H];              // gi (fp16)
__device__ __half g_mh [NNODES * H];                  // msg (fp16)
__device__ __half g_wh [(128 + 384 + 384) * H];       // W_msg | W_ih | W_hh (fp16)
__device__ int    g_deg [NNODES];
__device__ int    g_off [NNODES + 1];
__device__ int    g_cur [NNODES];
__device__ int    g_perm[NEDGES];
__device__ int    g_bsum[NSB];
__device__ int    g_bpre[NSB];

// ---------------- helpers ----------------
__device__ __forceinline__ uint32_t smem_u32(const void* p) {
    uint32_t a;
    asm("{ .reg .u64 t; cvta.to.shared.u64 t, %1; cvt.u32.u64 %0, t; }"
        : "=r"(a) : "l"(p));
    return a;
}
#define LDSM4(R, addr) \
    asm volatile("ldmatrix.sync.aligned.m8n8.x4.shared.b16 {%0,%1,%2,%3}, [%4];" \
        : "=r"((R)[0]), "=r"((R)[1]), "=r"((R)[2]), "=r"((R)[3]) : "r"(addr))
#define MMA_FP16(D, A, B0, B1) \
    asm volatile("mma.sync.aligned.m16n8k16.row.col.f32.f16.f16.f32 " \
        "{%0,%1,%2,%3}, {%4,%5,%6,%7}, {%8,%9}, {%0,%1,%2,%3};" \
        : "+f"((D)[0]), "+f"((D)[1]), "+f"((D)[2]), "+f"((D)[3]) \
        : "r"((A)[0]), "r"((A)[1]), "r"((A)[2]), "r"((A)[3]), "r"(B0), "r"(B1))

__device__ __forceinline__ uint2 cvt4h(float4 v) {
    __half2 a = __floats2half2_rn(v.x, v.y);
    __half2 b = __floats2half2_rn(v.z, v.w);
    uint2 r;
    r.x = *(uint32_t*)&a;
    r.y = *(uint32_t*)&b;
    return r;
}
__device__ __forceinline__ uint4 cvt8h(const float4* s) {
    uint2 a = cvt4h(s[0]), b = cvt4h(s[1]);
    return make_uint4(a.x, a.y, b.x, b.y);
}

// ---------------- graph prep ----------------
__global__ void zero_deg_kernel() {
    int i = blockIdx.x * blockDim.x + threadIdx.x;
    if (i < NNODES) g_deg[i] = 0;
}
__global__ void count_kernel(const int* __restrict__ edge_index) {
    int e = blockIdx.x * blockDim.x + threadIdx.x;
    if (e < NEDGES) atomicAdd(&g_deg[edge_index[NEDGES + e]], 1);
}
__global__ void scan1_kernel() {
    int tid = threadIdx.x;
    int i = blockIdx.x * SBLK + tid;
    int v = (i < NNODES) ? g_deg[i] : 0;
    #pragma unroll
    for (int o = 16; o > 0; o >>= 1) v += __shfl_down_sync(0xffffffffu, v, o);
    __shared__ int ws[SBLK / 32];
    if ((tid & 31) == 0) ws[tid >> 5] = v;
    __syncthreads();
    if (tid < 32) {
        int s = (tid < SBLK / 32) ? ws[tid] : 0;
        #pragma unroll
        for (int o = 16; o > 0; o >>= 1) s += __shfl_down_sync(0xffffffffu, s, o);
        if (tid == 0) g_bsum[blockIdx.x] = s;
    }
}
__global__ void scan2_kernel() {
    __shared__ int s[128];
    int tid = threadIdx.x;
    int v = (tid < NSB) ? g_bsum[tid] : 0;
    s[tid] = v;
    __syncthreads();
    #pragma unroll
    for (int o = 1; o < 128; o <<= 1) {
        int y = (tid >= o) ? s[tid - o] : 0;
        __syncthreads();
        s[tid] += y;
        __syncthreads();
    }
    if (tid < NSB) g_bpre[tid] = s[tid] - v;
    if (tid == 127) g_off[NNODES] = s[127];
}
__global__ void scan3_kernel() {
    int tid = threadIdx.x;
    int i = blockIdx.x * SBLK + tid;
    int v = (i < NNODES) ? g_deg[i] : 0;
    int lane = tid & 31, wid = tid >> 5;
    int x = v;
    #pragma unroll
    for (int o = 1; o < 32; o <<= 1) {
        int y = __shfl_up_sync(0xffffffffu, x, o);
        if (lane >= o) x += y;
    }
    __shared__ int wsum[SBLK / 32];
    if (lane == 31) wsum[wid] = x;
    __syncthreads();
    if (wid == 0) {
        int w = (lane < SBLK / 32) ? wsum[lane] : 0;
        #pragma unroll
        for (int o = 1; o < SBLK / 32; o <<= 1) {
            int y = __shfl_up_sync(0xffffffffu, w, o);
            if (lane >= o) w += y;
        }
        if (lane < SBLK / 32) wsum[lane] = w;
    }
    __syncthreads();
    int excl = x - v + (wid > 0 ? wsum[wid - 1] : 0) + g_bpre[blockIdx.x];
    if (i < NNODES) { g_off[i] = excl; g_cur[i] = excl; }
}
__global__ void scatter_kernel(const int* __restrict__ edge_index,
                               const int* __restrict__ etype) {
    int e = blockIdx.x * blockDim.x + threadIdx.x;
    if (e < NEDGES) {
        int d = edge_index[NEDGES + e];
        int s = edge_index[e];
        int t = etype[e];
        t = min(max(t, 0), NTYPES - 1);
        int pos = atomicAdd(&g_cur[d], 1);
        g_perm[pos] = (s << 4) | t;
    }
}

// ---------------- weight convert (fp32 -> fp16, one plane) -------------------
__global__ void convert_w_kernel(const float* __restrict__ Wm,
                                 const float* __restrict__ Wi,
                                 const float* __restrict__ Wh) {
    int i = blockIdx.x * blockDim.x + threadIdx.x;
    const int S1 = 128 * 32, S2 = (128 + 384) * 32, S3 = (128 + 768) * 32;
    if (i >= S3) return;
    float4 v;
    if (i < S1)       v = ((const float4*)Wm)[i];
    else if (i < S2)  v = ((const float4*)Wi)[i - S1];
    else              v = ((const float4*)Wh)[i - S2];
    ((uint2*)g_wh)[i] = cvt4h(v);
}

// ---------------- aggregate: warp per node, fp16 gather, MLP=4 ---------------
__global__ void aggregate_kernel(const float* __restrict__ emb, int base, int count) {
    int warp = (blockIdx.x * blockDim.x + threadIdx.x) >> 5;
    int lane = threadIdx.x & 31;
    if (warp >= count) return;
    int node = base + warp;
    int s0 = g_off[node];
    int s1 = g_off[node + 1];
    float4 acc = make_float4(0.f, 0.f, 0.f, 0.f);
    int i = s0;
    for (; i + 4 <= s1; i += 4) {
        int p0 = g_perm[i],     p1 = g_perm[i + 1];
        int p2 = g_perm[i + 2], p3 = g_perm[i + 3];
        uint2 u0 = *((const uint2*)(g_hWh + (size_t)(p0 >> 4) * H) + lane);
        uint2 u1 = *((const uint2*)(g_hWh + (size_t)(p1 >> 4) * H) + lane);
        uint2 u2 = *((const uint2*)(g_hWh + (size_t)(p2 >> 4) * H) + lane);
        uint2 u3 = *((const uint2*)(g_hWh + (size_t)(p3 >> 4) * H) + lane);
        float4 e0 = *((const float4*)(emb + (size_t)(p0 & 15) * H) + lane);
        float4 e1 = *((const float4*)(emb + (size_t)(p1 & 15) * H) + lane);
        float4 e2 = *((const float4*)(emb + (size_t)(p2 & 15) * H) + lane);
        float4 e3 = *((const float4*)(emb + (size_t)(p3 & 15) * H) + lane);
        float2 a0 = __half22float2(*(__half2*)&u0.x), a1 = __half22float2(*(__half2*)&u0.y);
        float2 b0 = __half22float2(*(__half2*)&u1.x), b1 = __half22float2(*(__half2*)&u1.y);
        float2 c0 = __half22float2(*(__half2*)&u2.x), c1 = __half22float2(*(__half2*)&u2.y);
        float2 d0 = __half22float2(*(__half2*)&u3.x), d1 = __half22float2(*(__half2*)&u3.y);
        acc.x += (a0.x + e0.x) + (b0.x + e1.x) + (c0.x + e2.x) + (d0.x + e3.x);
        acc.y += (a0.y + e0.y) + (b0.y + e1.y) + (c0.y + e2.y) + (d0.y + e3.y);
        acc.z += (a1.x + e0.z) + (b1.x + e1.z) + (c1.x + e2.z) + (d1.x + e3.z);
        acc.w += (a1.y + e0.w) + (b1.y + e1.w) + (c1.y + e2.w) + (d1.y + e3.w);
    }
    for (; i < s1; i++) {
        int p = g_perm[i];
        uint2 u = *((const uint2*)(g_hWh + (size_t)(p >> 4) * H) + lane);
        float2 f0 = __half22float2(*(__half2*)&u.x);
        float2 f1 = __half22float2(*(__half2*)&u.y);
        float4 ev = *((const float4*)(emb + (size_t)(p & 15) * H) + lane);
        acc.x += f0.x + ev.x;  acc.y += f0.y + ev.y;
        acc.z += f1.x + ev.z;  acc.w += f1.y + ev.w;
    }
    ((uint2*)(g_mh + (size_t)node * H))[lane] = cvt4h(acc);
}

// ---------------- fp16 1-pass GEMM, 128x128 block tile, fp16 output ----------
template <bool F32A>
__global__ __launch_bounds__(256)
void mma_gemm(const float* __restrict__ Afp, const __half* __restrict__ Ah,
              const __half* __restrict__ Bh,
              const float* __restrict__ bias, __half* __restrict__ C,
              int M, int N, int mblk_off) {
    extern __shared__ __half smh[];
    __half* sA = smh;                 // [128][PITCH]
    __half* sB = smh + 128 * PITCH;   // [128][PITCH]

    const int tid = threadIdx.x;
    const int m0 = (blockIdx.x + mblk_off) * 128;
    const int n0 = blockIdx.y * 128;

    for (int i = tid; i < 128 * 16; i += 256) {
        int r = i >> 4, c = i & 15;
        int gr = m0 + r;
        uint4 vh = make_uint4(0, 0, 0, 0);
        if (gr < M) {
            if (F32A) vh = cvt8h((const float4*)(Afp + (size_t)gr * H + c * 8));
            else      vh = *(const uint4*)(Ah + (size_t)gr * H + c * 8);
        }
        *(uint4*)(sA + r * PITCH + c * 8) = vh;
        int gn = n0 + r;
        *(uint4*)(sB + r * PITCH + c * 8) = *(const uint4*)(Bh + (size_t)gn * H + c * 8);
    }
    __syncthreads();

    const int lane = tid & 31;
    const int w = tid >> 5;
    const int wm = (w & 3) * 32;
    const int wn = (w >> 2) * 64;

    float d[2][8][4];
    #pragma unroll
    for (int mt = 0; mt < 2; mt++)
        #pragma unroll
        for (int nt = 0; nt < 8; nt++)
            #pragma unroll
            for (int q = 0; q < 4; q++) d[mt][nt][q] = 0.f;

    const uint32_t sbase = smem_u32(smh);
    const int t8 = lane >> 3, r8 = lane & 7;
    uint32_t aA[2];
    #pragma unroll
    for (int mt = 0; mt < 2; mt++) {
        int row = wm + mt * 16 + (t8 & 1) * 8 + r8;
        aA[mt] = sbase + (uint32_t)(row * PITCH + (t8 >> 1) * 8) * 2;
    }
    uint32_t aB[4];
    #pragma unroll
    for (int g = 0; g < 4; g++) {
        int row = wn + g * 16 + (t8 >> 1) * 8 + r8;
        aB[g] = sbase + 128 * PITCH * 2 + (uint32_t)(row * PITCH + (t8 & 1) * 8) * 2;
    }

    #pragma unroll
    for (int kk = 0; kk < 8; kk++) {
        const uint32_t ko = kk * 32;
        uint32_t a[2][4], b[4][4];
        #pragma unroll
        for (int mt = 0; mt < 2; mt++) LDSM4(a[mt], aA[mt] + ko);
        #pragma unroll
        for (int g = 0; g < 4; g++)   LDSM4(b[g], aB[g] + ko);
        #pragma unroll
        for (int mt = 0; mt < 2; mt++)
            #pragma unroll
            for (int nt = 0; nt < 8; nt++) {
                int g = nt >> 1, o = (nt & 1) * 2;
                MMA_FP16(d[mt][nt], a[mt], b[g][o], b[g][o + 1]);
            }
    }

    const int rr = lane >> 2, c2 = (lane & 3) * 2;
    #pragma unroll
    for (int mt = 0; mt < 2; mt++)
        #pragma unroll
        for (int nt = 0; nt < 8; nt++) {
            int col = n0 + wn + nt * 8 + c2;
            float b0 = bias[col], b1 = bias[col + 1];
            int row0 = m0 + wm + mt * 16 + rr;
            if (row0 < M) {
                __half2 hv = __floats2half2_rn(d[mt][nt][0] + b0, d[mt][nt][1] + b1);
                *(uint32_t*)(C + (size_t)row0 * N + col) = *(uint32_t*)&hv;
            }
            int row1 = row0 + 8;
            if (row1 < M) {
                __half2 hv = __floats2half2_rn(d[mt][nt][2] + b0, d[mt][nt][3] + b1);
                *(uint32_t*)(C + (size_t)row1 * N + col) = *(uint32_t*)&hv;
            }
        }
}

// ---------------- fused gh GEMM + GRU gates: 128 rows x ALL 128 cols ---------
// 512 thr / 16 warps (4m x 4n); warp tile 32m x 32c x 3 slabs. grid.y = 1.
__global__ __launch_bounds__(512)
void gh_gates_kernel(const float* __restrict__ h,
                     const __half* __restrict__ Bh,
                     const float* __restrict__ b_hh,
                     const __half* __restrict__ gi,
                     float* __restrict__ out, int M, int mblk_off) {
    extern __shared__ __half smh[];
    __half* sB = smh + 128 * PITCH;   // [384][PITCH] = full W_hh

    const int tid = threadIdx.x;
    const int m0 = (blockIdx.x + mblk_off) * 128;

    for (int i = tid; i < 128 * 16; i += 512) {
        int r = i >> 4, c = i & 15;
        int gr = m0 + r;
        uint4 vh = make_uint4(0, 0, 0, 0);
        if (gr < M) vh = cvt8h((const float4*)(h + (size_t)gr * H + c * 8));
        *(uint4*)(smh + r * PITCH + c * 8) = vh;
    }
    for (int i = tid; i < 384 * 16; i += 512) {
        int r = i >> 4, c = i & 15;
        *(uint4*)(sB + r * PITCH + c * 8) = *(const uint4*)(Bh + (size_t)r * H + c * 8);
    }
    __syncthreads();

    const int lane = tid & 31;
    const int w = tid >> 5;
    const int wm = (w & 3) * 32;       // 4 m-groups
    const int wn = (w >> 2) * 32;      // 4 n-groups of 32 cols

    float d[3][2][4][4];
    #pragma unroll
    for (int s = 0; s < 3; s++)
        #pragma unroll
        for (int mt = 0; mt < 2; mt++)
            #pragma unroll
            for (int nt = 0; nt < 4; nt++)
                #pragma unroll
                for (int q = 0; q < 4; q++) d[s][mt][nt][q] = 0.f;

    const uint32_t sbase = smem_u32(smh);
    const int t8 = lane >> 3, r8 = lane & 7;
    uint32_t aA[2];
    #pragma unroll
    for (int mt = 0; mt < 2; mt++) {
        int row = wm + mt * 16 + (t8 & 1) * 8 + r8;
        aA[mt] = sbase + (uint32_t)(row * PITCH + (t8 >> 1) * 8) * 2;
    }
    const uint32_t Bbase = sbase + 128 * PITCH * 2;
    uint32_t aB[3][2];
    #pragma unroll
    for (int s = 0; s < 3; s++)
        #pragma unroll
        for (int g = 0; g < 2; g++) {
            int row = s * 128 + wn + g * 16 + (t8 >> 1) * 8 + r8;
            aB[s][g] = Bbase + (uint32_t)(row * PITCH + (t8 & 1) * 8) * 2;
        }

    #pragma unroll
    for (int kk = 0; kk < 8; kk++) {
        const uint32_t ko = kk * 32;
        uint32_t a[2][4];
        #pragma unroll
        for (int mt = 0; mt < 2; mt++) LDSM4(a[mt], aA[mt] + ko);
        #pragma unroll
        for (int s = 0; s < 3; s++) {
            uint32_t b[2][4];
            LDSM4(b[0], aB[s][0] + ko);
            LDSM4(b[1], aB[s][1] + ko);
            #pragma unroll
            for (int mt = 0; mt < 2; mt++)
                #pragma unroll
                for (int nt = 0; nt < 4; nt++) {
                    int g = nt >> 1, o = (nt & 1) * 2;
                    MMA_FP16(d[s][mt][nt], a[mt], b[g][o], b[g][o + 1]);
                }
        }
    }

    const int rr = lane >> 2, c2 = (lane & 3) * 2;
    #pragma unroll
    for (int mt = 0; mt < 2; mt++)
        #pragma unroll
        for (int nt = 0; nt < 4; nt++) {
            int col = wn + nt * 8 + c2;
            float bhr0 = b_hh[col],       bhr1 = b_hh[col + 1];
            float bhz0 = b_hh[128 + col], bhz1 = b_hh[128 + col + 1];
            float bhn0 = b_hh[256 + col], bhn1 = b_hh[256 + col + 1];
            #pragma unroll
            for (int half = 0; half < 2; half++) {
                int row = m0 + wm + mt * 16 + rr + half * 8;
                if (row >= M) continue;
                size_t gb = (size_t)row * 384 + col;
                float2 gir = __half22float2(*(const __half2*)(gi + gb));
                float2 giz = __half22float2(*(const __half2*)(gi + gb + 128));
                float2 gin = __half22float2(*(const __half2*)(gi + gb + 256));
                float ghr0 = d[0][mt][nt][half * 2]     + bhr0;
                float ghr1 = d[0][mt][nt][half * 2 + 1] + bhr1;
                float ghz0 = d[1][mt][nt][half * 2]     + bhz0;
                float ghz1 = d[1][mt][nt][half * 2 + 1] + bhz1;
                float ghn0 = d[2][mt][nt][half * 2]     + bhn0;
                float ghn1 = d[2][mt][nt][half * 2 + 1] + bhn1;
                float r0 = 1.f / (1.f + __expf(-(gir.x + ghr0)));
                float r1 = 1.f / (1.f + __expf(-(gir.y + ghr1)));
                float z0 = 1.f / (1.f + __expf(-(giz.x + ghz0)));
                float z1 = 1.f / (1.f + __expf(-(giz.y + ghz1)));
                float n0v = tanhf(gin.x + r0 * ghn0);
                float n1v = tanhf(gin.y + r1 * ghn1);
                float2 hv = *(const float2*)(h + (size_t)row * H + col);
                float2 o;
                o.x = (1.f - z0) * n0v + z0 * hv.x;
                o.y = (1.f - z1) * n1v + z1 * hv.y;
                *(float2*)(out + (size_t)row * H + col) = o;
            }
        }
}

// ---------------- launch ----------------
static cudaStream_t s_prep = 0;
static cudaEvent_t  s_ev_fork = 0, s_ev_hw = 0, s_ev_a1 = 0, s_ev_a2 = 0;
static cudaEvent_t  s_ev_gi1 = 0, s_ev_gi2 = 0, s_ev_done = 0;

extern "C" void kernel_launch(void* const* d_in, const int* in_sizes, int n_in,
                              void* d_out, int out_size) {
    const float* h     = (const float*)d_in[0];
    const int*   eidx  = (const int*)  d_in[1];
    const int*   etype = (const int*)  d_in[2];
    const float* W_msg = (const float*)d_in[4];
    const float* b_msg = (const float*)d_in[5];
    const float* emb   = (const float*)d_in[6];
    const float* W_ih  = (const float*)d_in[7];
    const float* W_hh  = (const float*)d_in[8];
    const float* b_ih  = (const float*)d_in[9];
    const float* b_hh  = (const float*)d_in[10];
    float* out = (float*)d_out;

    if (s_prep == 0) {
        cudaStreamCreateWithFlags(&s_prep, cudaStreamNonBlocking);
        cudaEventCreateWithFlags(&s_ev_fork, cudaEventDisableTiming);
        cudaEventCreateWithFlags(&s_ev_hw,   cudaEventDisableTiming);
        cudaEventCreateWithFlags(&s_ev_a1,   cudaEventDisableTiming);
        cudaEventCreateWithFlags(&s_ev_a2,   cudaEventDisableTiming);
        cudaEventCreateWithFlags(&s_ev_gi1,  cudaEventDisableTiming);
        cudaEventCreateWithFlags(&s_ev_gi2,  cudaEventDisableTiming);
        cudaEventCreateWithFlags(&s_ev_done, cudaEventDisableTiming);
    }

    __half *hWh, *gih, *mh, *wh;
    cudaGetSymbolAddress((void**)&hWh, g_hWh);
    cudaGetSymbolAddress((void**)&gih, g_gih);
    cudaGetSymbolAddress((void**)&mh,  g_mh);
    cudaGetSymbolAddress((void**)&wh,  g_wh);

    cudaFuncSetAttribute(mma_gemm<true>,  cudaFuncAttributeMaxDynamicSharedMemorySize, MMA_SMEM);
    cudaFuncSetAttribute(mma_gemm<false>, cudaFuncAttributeMaxDynamicSharedMemorySize, MMA_SMEM);
    cudaFuncSetAttribute(gh_gates_kernel, cudaFuncAttributeMaxDynamicSharedMemorySize, GGF_SMEM);

    const int W_IH_OFF = 128 * H;
    const int W_HH_OFF = (128 + 384) * H;

    // fork
    cudaEventRecord(s_ev_fork, 0);
    cudaStreamWaitEvent(s_prep, s_ev_fork, 0);

    // prep stream: CSR build
    zero_deg_kernel<<<(NNODES + 255) / 256, 256, 0, s_prep>>>();
    count_kernel  <<<(NEDGES + 255) / 256, 256, 0, s_prep>>>(eidx);
    scan1_kernel<<<NSB, SBLK, 0, s_prep>>>();
    scan2_kernel<<<1, 128, 0, s_prep>>>();
    scan3_kernel<<<NSB, SBLK, 0, s_prep>>>();
    scatter_kernel<<<(NEDGES + 255) / 256, 256, 0, s_prep>>>(eidx, etype);

    // main stream: weight convert -> hW GEMM (fp16 out)
    convert_w_kernel<<<((128 + 768) * 32 + 255) / 256, 256>>>(W_msg, W_ih, W_hh);
    mma_gemm<true><<<dim3(GB_TOT, 1), 256, MMA_SMEM>>>(h, nullptr, wh,
                                                       b_msg, hWh, NNODES, 128, 0);
    cudaEventRecord(s_ev_hw, 0);

    // prep stream: aggregate in two halves (needs hW + CSR)
    cudaStreamWaitEvent(s_prep, s_ev_hw, 0);
    aggregate_kernel<<<(NHALF1 * 32 + 255) / 256, 256, 0, s_prep>>>(emb, 0, NHALF1);
    cudaEventRecord(s_ev_a1, s_prep);
    aggregate_kernel<<<(NHALF2 * 32 + 255) / 256, 256, 0, s_prep>>>(emb, NHALF1, NHALF2);
    cudaEventRecord(s_ev_a2, s_prep);

    // main stream: gi GEMM halves (fp16 out), each unblocked by its aggregate half
    cudaStreamWaitEvent(0, s_ev_a1, 0);
    mma_gemm<false><<<dim3(GB1, 3), 256, MMA_SMEM>>>(nullptr, mh, wh + W_IH_OFF,
                                                     b_ih, gih, NNODES, 384, 0);
    cudaEventRecord(s_ev_gi1, 0);
    cudaStreamWaitEvent(0, s_ev_a2, 0);
    mma_gemm<false><<<dim3(GB2, 3), 256, MMA_SMEM>>>(nullptr, mh, wh + W_IH_OFF,
                                                     b_ih, gih, NNODES, 384, GB1);
    cudaEventRecord(s_ev_gi2, 0);

    // prep stream: gh+gates halves, overlapping gi half2 on main
    cudaStreamWaitEvent(s_prep, s_ev_gi1, 0);
    gh_gates_kernel<<<dim3(GB1, 1), 512, GGF_SMEM, s_prep>>>(h, wh + W_HH_OFF,
                                                             b_hh, gih, out, NNODES, 0);
    cudaStreamWaitEvent(s_prep, s_ev_gi2, 0);
    gh_gates_kernel<<<dim3(GB2, 1), 512, GGF_SMEM, s_prep>>>(h, wh + W_HH_OFF,
                                                             b_hh, gih, out, NNODES, GB1);
    cudaEventRecord(s_ev_done, s_prep);

    // join back to origin stream for capture
    cudaStreamWaitEvent(0, s_ev_done, 0);
}

// round 15
// speedup vs baseline: 1.0883x; 1.0883x over previous
#include <cuda_runtime.h>
#include <cuda_fp16.h>
#include <math.h>
#include <stdint.h>

#define H       128
#define NNODES  50000
#define NEDGES  600000
#define NTYPES  9

#define SBLK    512
#define NSB     ((NNODES + SBLK - 1) / SBLK)   // 98

#define PITCH   136                 // fp16 units; 272B rows, ldmatrix-friendly
#define MMA_SMEM ((128*PITCH + 128*PITCH) * 2)    // 69632 B -> 3 CTA/SM
#define GGF_SMEM ((128*PITCH + 192*PITCH) * 2)    // 87040 B -> 2 CTA/SM, 512 thr

#define GB_TOT  ((NNODES + 127) / 128)   // 391
#define GB1     196
#define GB2     (GB_TOT - GB1)           // 195
#define NHALF1  (GB1 * 128)              // 25088
#define NHALF2  (NNODES - NHALF1)        // 24912

// ---------------- scratch ----------------
__device__ __half g_hWh[NNODES * H];                  // hW (fp16)
__device__ __half g_gih[NNODES * 3 * H];              // gi (fp16)
__device__ __half g_mh [NNODES * H];                  // msg (fp16)
__device__ __half g_wh [(128 + 384 + 384) * H];       // W_msg | W_ih | W_hh (fp16)
__device__ int    g_deg [NNODES];
__device__ int    g_off [NNODES + 1];
__device__ int    g_cur [NNODES];
__device__ int    g_perm[NEDGES];
__device__ int    g_bsum[NSB];
__device__ int    g_bpre[NSB];

// ---------------- helpers ----------------
__device__ __forceinline__ uint32_t smem_u32(const void* p) {
    uint32_t a;
    asm("{ .reg .u64 t; cvta.to.shared.u64 t, %1; cvt.u32.u64 %0, t; }"
        : "=r"(a) : "l"(p));
    return a;
}
#define LDSM4(R, addr) \
    asm volatile("ldmatrix.sync.aligned.m8n8.x4.shared.b16 {%0,%1,%2,%3}, [%4];" \
        : "=r"((R)[0]), "=r"((R)[1]), "=r"((R)[2]), "=r"((R)[3]) : "r"(addr))
#define MMA_FP16(D, A, B0, B1) \
    asm volatile("mma.sync.aligned.m16n8k16.row.col.f32.f16.f16.f32 " \
        "{%0,%1,%2,%3}, {%4,%5,%6,%7}, {%8,%9}, {%0,%1,%2,%3};" \
        : "+f"((D)[0]), "+f"((D)[1]), "+f"((D)[2]), "+f"((D)[3]) \
        : "r"((A)[0]), "r"((A)[1]), "r"((A)[2]), "r"((A)[3]), "r"(B0), "r"(B1))

__device__ __forceinline__ uint2 cvt4h(float4 v) {
    __half2 a = __floats2half2_rn(v.x, v.y);
    __half2 b = __floats2half2_rn(v.z, v.w);
    uint2 r;
    r.x = *(uint32_t*)&a;
    r.y = *(uint32_t*)&b;
    return r;
}
__device__ __forceinline__ uint4 cvt8h(const float4* s) {
    uint2 a = cvt4h(s[0]), b = cvt4h(s[1]);
    return make_uint4(a.x, a.y, b.x, b.y);
}

// ---------------- graph prep ----------------
__global__ void zero_deg_kernel() {
    int i = blockIdx.x * blockDim.x + threadIdx.x;
    if (i < NNODES) g_deg[i] = 0;
}
__global__ void count_kernel(const int* __restrict__ edge_index) {
    int e = blockIdx.x * blockDim.x + threadIdx.x;
    if (e < NEDGES) atomicAdd(&g_deg[edge_index[NEDGES + e]], 1);
}
__global__ void scan1_kernel() {
    int tid = threadIdx.x;
    int i = blockIdx.x * SBLK + tid;
    int v = (i < NNODES) ? g_deg[i] : 0;
    #pragma unroll
    for (int o = 16; o > 0; o >>= 1) v += __shfl_down_sync(0xffffffffu, v, o);
    __shared__ int ws[SBLK / 32];
    if ((tid & 31) == 0) ws[tid >> 5] = v;
    __syncthreads();
    if (tid < 32) {
        int s = (tid < SBLK / 32) ? ws[tid] : 0;
        #pragma unroll
        for (int o = 16; o > 0; o >>= 1) s += __shfl_down_sync(0xffffffffu, s, o);
        if (tid == 0) g_bsum[blockIdx.x] = s;
    }
}
__global__ void scan2_kernel() {
    __shared__ int s[128];
    int tid = threadIdx.x;
    int v = (tid < NSB) ? g_bsum[tid] : 0;
    s[tid] = v;
    __syncthreads();
    #pragma unroll
    for (int o = 1; o < 128; o <<= 1) {
        int y = (tid >= o) ? s[tid - o] : 0;
        __syncthreads();
        s[tid] += y;
        __syncthreads();
    }
    if (tid < NSB) g_bpre[tid] = s[tid] - v;
    if (tid == 127) g_off[NNODES] = s[127];
}
__global__ void scan3_kernel() {
    int tid = threadIdx.x;
    int i = blockIdx.x * SBLK + tid;
    int v = (i < NNODES) ? g_deg[i] : 0;
    int lane = tid & 31, wid = tid >> 5;
    int x = v;
    #pragma unroll
    for (int o = 1; o < 32; o <<= 1) {
        int y = __shfl_up_sync(0xffffffffu, x, o);
        if (lane >= o) x += y;
    }
    __shared__ int wsum[SBLK / 32];
    if (lane == 31) wsum[wid] = x;
    __syncthreads();
    if (wid == 0) {
        int w = (lane < SBLK / 32) ? wsum[lane] : 0;
        #pragma unroll
        for (int o = 1; o < SBLK / 32; o <<= 1) {
            int y = __shfl_up_sync(0xffffffffu, w, o);
            if (lane >= o) w += y;
        }
        if (lane < SBLK / 32) wsum[lane] = w;
    }
    __syncthreads();
    int excl = x - v + (wid > 0 ? wsum[wid - 1] : 0) + g_bpre[blockIdx.x];
    if (i < NNODES) { g_off[i] = excl; g_cur[i] = excl; }
}
__global__ void scatter_kernel(const int* __restrict__ edge_index,
                               const int* __restrict__ etype) {
    int e = blockIdx.x * blockDim.x + threadIdx.x;
    if (e < NEDGES) {
        int d = edge_index[NEDGES + e];
        int s = edge_index[e];
        int t = etype[e];
        t = min(max(t, 0), NTYPES - 1);
        int pos = atomicAdd(&g_cur[d], 1);
        g_perm[pos] = (s << 4) | t;
    }
}

// ---------------- weight convert (fp32 -> fp16, one plane) -------------------
__global__ void convert_w_kernel(const float* __restrict__ Wm,
                                 const float* __restrict__ Wi,
                                 const float* __restrict__ Wh) {
    int i = blockIdx.x * blockDim.x + threadIdx.x;
    const int S1 = 128 * 32, S2 = (128 + 384) * 32, S3 = (128 + 768) * 32;
    if (i >= S3) return;
    float4 v;
    if (i < S1)       v = ((const float4*)Wm)[i];
    else if (i < S2)  v = ((const float4*)Wi)[i - S1];
    else              v = ((const float4*)Wh)[i - S2];
    ((uint2*)g_wh)[i] = cvt4h(v);
}

// ---------------- aggregate: warp per node, fp16 gather, MLP=4 ---------------
__global__ void aggregate_kernel(const float* __restrict__ emb, int base, int count) {
    int warp = (blockIdx.x * blockDim.x + threadIdx.x) >> 5;
    int lane = threadIdx.x & 31;
    if (warp >= count) return;
    int node = base + warp;
    int s0 = g_off[node];
    int s1 = g_off[node + 1];
    float4 acc = make_float4(0.f, 0.f, 0.f, 0.f);
    int i = s0;
    for (; i + 4 <= s1; i += 4) {
        int p0 = g_perm[i],     p1 = g_perm[i + 1];
        int p2 = g_perm[i + 2], p3 = g_perm[i + 3];
        uint2 u0 = *((const uint2*)(g_hWh + (size_t)(p0 >> 4) * H) + lane);
        uint2 u1 = *((const uint2*)(g_hWh + (size_t)(p1 >> 4) * H) + lane);
        uint2 u2 = *((const uint2*)(g_hWh + (size_t)(p2 >> 4) * H) + lane);
        uint2 u3 = *((const uint2*)(g_hWh + (size_t)(p3 >> 4) * H) + lane);
        float4 e0 = *((const float4*)(emb + (size_t)(p0 & 15) * H) + lane);
        float4 e1 = *((const float4*)(emb + (size_t)(p1 & 15) * H) + lane);
        float4 e2 = *((const float4*)(emb + (size_t)(p2 & 15) * H) + lane);
        float4 e3 = *((const float4*)(emb + (size_t)(p3 & 15) * H) + lane);
        float2 a0 = __half22float2(*(__half2*)&u0.x), a1 = __half22float2(*(__half2*)&u0.y);
        float2 b0 = __half22float2(*(__half2*)&u1.x), b1 = __half22float2(*(__half2*)&u1.y);
        float2 c0 = __half22float2(*(__half2*)&u2.x), c1 = __half22float2(*(__half2*)&u2.y);
        float2 d0 = __half22float2(*(__half2*)&u3.x), d1 = __half22float2(*(__half2*)&u3.y);
        acc.x += (a0.x + e0.x) + (b0.x + e1.x) + (c0.x + e2.x) + (d0.x + e3.x);
        acc.y += (a0.y + e0.y) + (b0.y + e1.y) + (c0.y + e2.y) + (d0.y + e3.y);
        acc.z += (a1.x + e0.z) + (b1.x + e1.z) + (c1.x + e2.z) + (d1.x + e3.z);
        acc.w += (a1.y + e0.w) + (b1.y + e1.w) + (c1.y + e2.w) + (d1.y + e3.w);
    }
    for (; i < s1; i++) {
        int p = g_perm[i];
        uint2 u = *((const uint2*)(g_hWh + (size_t)(p >> 4) * H) + lane);
        float2 f0 = __half22float2(*(__half2*)&u.x);
        float2 f1 = __half22float2(*(__half2*)&u.y);
        float4 ev = *((const float4*)(emb + (size_t)(p & 15) * H) + lane);
        acc.x += f0.x + ev.x;  acc.y += f0.y + ev.y;
        acc.z += f1.x + ev.z;  acc.w += f1.y + ev.w;
    }
    ((uint2*)(g_mh + (size_t)node * H))[lane] = cvt4h(acc);
}

// ---------------- fp16 1-pass GEMM, 128x128 block tile, fp16 output ----------
template <bool F32A>
__global__ __launch_bounds__(256)
void mma_gemm(const float* __restrict__ Afp, const __half* __restrict__ Ah,
              const __half* __restrict__ Bh,
              const float* __restrict__ bias, __half* __restrict__ C,
              int M, int N, int mblk_off) {
    extern __shared__ __half smh[];
    __half* sA = smh;                 // [128][PITCH]
    __half* sB = smh + 128 * PITCH;   // [128][PITCH]

    const int tid = threadIdx.x;
    const int m0 = (blockIdx.x + mblk_off) * 128;
    const int n0 = blockIdx.y * 128;

    for (int i = tid; i < 128 * 16; i += 256) {
        int r = i >> 4, c = i & 15;
        int gr = m0 + r;
        uint4 vh = make_uint4(0, 0, 0, 0);
        if (gr < M) {
            if (F32A) vh = cvt8h((const float4*)(Afp + (size_t)gr * H + c * 8));
            else      vh = *(const uint4*)(Ah + (size_t)gr * H + c * 8);
        }
        *(uint4*)(sA + r * PITCH + c * 8) = vh;
        int gn = n0 + r;
        *(uint4*)(sB + r * PITCH + c * 8) = *(const uint4*)(Bh + (size_t)gn * H + c * 8);
    }
    __syncthreads();

    const int lane = tid & 31;
    const int w = tid >> 5;
    const int wm = (w & 3) * 32;
    const int wn = (w >> 2) * 64;

    float d[2][8][4];
    #pragma unroll
    for (int mt = 0; mt < 2; mt++)
        #pragma unroll
        for (int nt = 0; nt < 8; nt++)
            #pragma unroll
            for (int q = 0; q < 4; q++) d[mt][nt][q] = 0.f;

    const uint32_t sbase = smem_u32(smh);
    const int t8 = lane >> 3, r8 = lane & 7;
    uint32_t aA[2];
    #pragma unroll
    for (int mt = 0; mt < 2; mt++) {
        int row = wm + mt * 16 + (t8 & 1) * 8 + r8;
        aA[mt] = sbase + (uint32_t)(row * PITCH + (t8 >> 1) * 8) * 2;
    }
    uint32_t aB[4];
    #pragma unroll
    for (int g = 0; g < 4; g++) {
        int row = wn + g * 16 + (t8 >> 1) * 8 + r8;
        aB[g] = sbase + 128 * PITCH * 2 + (uint32_t)(row * PITCH + (t8 & 1) * 8) * 2;
    }

    #pragma unroll
    for (int kk = 0; kk < 8; kk++) {
        const uint32_t ko = kk * 32;
        uint32_t a[2][4], b[4][4];
        #pragma unroll
        for (int mt = 0; mt < 2; mt++) LDSM4(a[mt], aA[mt] + ko);
        #pragma unroll
        for (int g = 0; g < 4; g++)   LDSM4(b[g], aB[g] + ko);
        #pragma unroll
        for (int mt = 0; mt < 2; mt++)
            #pragma unroll
            for (int nt = 0; nt < 8; nt++) {
                int g = nt >> 1, o = (nt & 1) * 2;
                MMA_FP16(d[mt][nt], a[mt], b[g][o], b[g][o + 1]);
            }
    }

    const int rr = lane >> 2, c2 = (lane & 3) * 2;
    #pragma unroll
    for (int mt = 0; mt < 2; mt++)
        #pragma unroll
        for (int nt = 0; nt < 8; nt++) {
            int col = n0 + wn + nt * 8 + c2;
            float b0 = bias[col], b1 = bias[col + 1];
            int row0 = m0 + wm + mt * 16 + rr;
            if (row0 < M) {
                __half2 hv = __floats2half2_rn(d[mt][nt][0] + b0, d[mt][nt][1] + b1);
                *(uint32_t*)(C + (size_t)row0 * N + col) = *(uint32_t*)&hv;
            }
            int row1 = row0 + 8;
            if (row1 < M) {
                __half2 hv = __floats2half2_rn(d[mt][nt][2] + b0, d[mt][nt][3] + b1);
                *(uint32_t*)(C + (size_t)row1 * N + col) = *(uint32_t*)&hv;
            }
        }
}

// ---------------- fused gh GEMM + GRU gates (round-13 config) ----------------
// Block: 128 rows x 64 gate-cols x 3 slabs; 512 thr / 16 warps; 2 CTA/SM.
__global__ __launch_bounds__(512)
void gh_gates_kernel(const float* __restrict__ h,
                     const __half* __restrict__ Bh,
                     const float* __restrict__ b_hh,
                     const __half* __restrict__ gi,
                     float* __restrict__ out, int M, int mblk_off) {
    extern __shared__ __half smh[];
    __half* sB = smh + 128 * PITCH;   // [192][PITCH]

    const int tid = threadIdx.x;
    const int m0 = (blockIdx.x + mblk_off) * 128;
    const int c0 = blockIdx.y * 64;

    for (int i = tid; i < 128 * 16; i += 512) {
        int r = i >> 4, c = i & 15;
        int gr = m0 + r;
        uint4 vh = make_uint4(0, 0, 0, 0);
        if (gr < M) vh = cvt8h((const float4*)(h + (size_t)gr * H + c * 8));
        *(uint4*)(smh + r * PITCH + c * 8) = vh;
    }
    for (int i = tid; i < 192 * 16; i += 512) {
        int r = i >> 4, c = i & 15;
        int s = r >> 6, rl = r & 63;
        int grow = s * 128 + c0 + rl;
        *(uint4*)(sB + r * PITCH + c * 8) = *(const uint4*)(Bh + (size_t)grow * H + c * 8);
    }
    __syncthreads();

    const int lane = tid & 31;
    const int w = tid >> 5;
    const int wm = (w & 3) * 32;       // 4 m-groups
    const int wn = (w >> 2) * 16;      // 4 n-groups of 16 cols

    float d[3][2][2][4];
    #pragma unroll
    for (int s = 0; s < 3; s++)
        #pragma unroll
        for (int mt = 0; mt < 2; mt++)
            #pragma unroll
            for (int nt = 0; nt < 2; nt++)
                #pragma unroll
                for (int q = 0; q < 4; q++) d[s][mt][nt][q] = 0.f;

    const uint32_t sbase = smem_u32(smh);
    const int t8 = lane >> 3, r8 = lane & 7;
    uint32_t aA[2];
    #pragma unroll
    for (int mt = 0; mt < 2; mt++) {
        int row = wm + mt * 16 + (t8 & 1) * 8 + r8;
        aA[mt] = sbase + (uint32_t)(row * PITCH + (t8 >> 1) * 8) * 2;
    }
    const uint32_t Bbase = sbase + 128 * PITCH * 2;
    uint32_t aB[3];
    #pragma unroll
    for (int s = 0; s < 3; s++) {
        int row = s * 64 + wn + (t8 >> 1) * 8 + r8;
        aB[s] = Bbase + (uint32_t)(row * PITCH + (t8 & 1) * 8) * 2;
    }

    #pragma unroll
    for (int kk = 0; kk < 8; kk++) {
        const uint32_t ko = kk * 32;
        uint32_t a[2][4];
        #pragma unroll
        for (int mt = 0; mt < 2; mt++) LDSM4(a[mt], aA[mt] + ko);
        #pragma unroll
        for (int s = 0; s < 3; s++) {
            uint32_t b[4];
            LDSM4(b, aB[s] + ko);
            #pragma unroll
            for (int mt = 0; mt < 2; mt++)
                #pragma unroll
                for (int nt = 0; nt < 2; nt++) {
                    int o = nt * 2;
                    MMA_FP16(d[s][mt][nt], a[mt], b[o], b[o + 1]);
                }
        }
    }

    const int rr = lane >> 2, c2 = (lane & 3) * 2;
    #pragma unroll
    for (int mt = 0; mt < 2; mt++)
        #pragma unroll
        for (int nt = 0; nt < 2; nt++) {
            int col = c0 + wn + nt * 8 + c2;
            float bhr0 = b_hh[col],       bhr1 = b_hh[col + 1];
            float bhz0 = b_hh[128 + col], bhz1 = b_hh[128 + col + 1];
            float bhn0 = b_hh[256 + col], bhn1 = b_hh[256 + col + 1];
            #pragma unroll
            for (int half = 0; half < 2; half++) {
                int row = m0 + wm + mt * 16 + rr + half * 8;
                if (row >= M) continue;
                size_t gb = (size_t)row * 384 + col;
                float2 gir = __half22float2(*(const __half2*)(gi + gb));
                float2 giz = __half22float2(*(const __half2*)(gi + gb + 128));
                float2 gin = __half22float2(*(const __half2*)(gi + gb + 256));
                float ghr0 = d[0][mt][nt][half * 2]     + bhr0;
                float ghr1 = d[0][mt][nt][half * 2 + 1] + bhr1;
                float ghz0 = d[1][mt][nt][half * 2]     + bhz0;
                float ghz1 = d[1][mt][nt][half * 2 + 1] + bhz1;
                float ghn0 = d[2][mt][nt][half * 2]     + bhn0;
                float ghn1 = d[2][mt][nt][half * 2 + 1] + bhn1;
                float r0 = 1.f / (1.f + __expf(-(gir.x + ghr0)));
                float r1 = 1.f / (1.f + __expf(-(gir.y + ghr1)));
                float z0 = 1.f / (1.f + __expf(-(giz.x + ghz0)));
                float z1 = 1.f / (1.f + __expf(-(giz.y + ghz1)));
                float n0v = tanhf(gin.x + r0 * ghn0);
                float n1v = tanhf(gin.y + r1 * ghn1);
                float2 hv = *(const float2*)(h + (size_t)row * H + col);
                float2 o;
                o.x = (1.f - z0) * n0v + z0 * hv.x;
                o.y = (1.f - z1) * n1v + z1 * hv.y;
                *(float2*)(out + (size_t)row * H + col) = o;
            }
        }
}

// ---------------- launch ----------------
static cudaStream_t s_prep = 0;
static cudaEvent_t  s_ev_fork = 0, s_ev_hw = 0, s_ev_a1 = 0, s_ev_a2 = 0;
static cudaEvent_t  s_ev_gi1 = 0, s_ev_gi2 = 0, s_ev_done = 0;

extern "C" void kernel_launch(void* const* d_in, const int* in_sizes, int n_in,
                              void* d_out, int out_size) {
    const float* h     = (const float*)d_in[0];
    const int*   eidx  = (const int*)  d_in[1];
    const int*   etype = (const int*)  d_in[2];
    const float* W_msg = (const float*)d_in[4];
    const float* b_msg = (const float*)d_in[5];
    const float* emb   = (const float*)d_in[6];
    const float* W_ih  = (const float*)d_in[7];
    const float* W_hh  = (const float*)d_in[8];
    const float* b_ih  = (const float*)d_in[9];
    const float* b_hh  = (const float*)d_in[10];
    float* out = (float*)d_out;

    if (s_prep == 0) {
        cudaStreamCreateWithFlags(&s_prep, cudaStreamNonBlocking);
        cudaEventCreateWithFlags(&s_ev_fork, cudaEventDisableTiming);
        cudaEventCreateWithFlags(&s_ev_hw,   cudaEventDisableTiming);
        cudaEventCreateWithFlags(&s_ev_a1,   cudaEventDisableTiming);
        cudaEventCreateWithFlags(&s_ev_a2,   cudaEventDisableTiming);
        cudaEventCreateWithFlags(&s_ev_gi1,  cudaEventDisableTiming);
        cudaEventCreateWithFlags(&s_ev_gi2,  cudaEventDisableTiming);
        cudaEventCreateWithFlags(&s_ev_done, cudaEventDisableTiming);
    }

    __half *hWh, *gih, *mh, *wh;
    cudaGetSymbolAddress((void**)&hWh, g_hWh);
    cudaGetSymbolAddress((void**)&gih, g_gih);
    cudaGetSymbolAddress((void**)&mh,  g_mh);
    cudaGetSymbolAddress((void**)&wh,  g_wh);

    cudaFuncSetAttribute(mma_gemm<true>,  cudaFuncAttributeMaxDynamicSharedMemorySize, MMA_SMEM);
    cudaFuncSetAttribute(mma_gemm<false>, cudaFuncAttributeMaxDynamicSharedMemorySize, MMA_SMEM);
    cudaFuncSetAttribute(gh_gates_kernel, cudaFuncAttributeMaxDynamicSharedMemorySize, GGF_SMEM);

    const int W_IH_OFF = 128 * H;
    const int W_HH_OFF = (128 + 384) * H;

    // fork
    cudaEventRecord(s_ev_fork, 0);
    cudaStreamWaitEvent(s_prep, s_ev_fork, 0);

    // prep stream: CSR build
    zero_deg_kernel<<<(NNODES + 255) / 256, 256, 0, s_prep>>>();
    count_kernel  <<<(NEDGES + 255) / 256, 256, 0, s_prep>>>(eidx);
    scan1_kernel<<<NSB, SBLK, 0, s_prep>>>();
    scan2_kernel<<<1, 128, 0, s_prep>>>();
    scan3_kernel<<<NSB, SBLK, 0, s_prep>>>();
    scatter_kernel<<<(NEDGES + 255) / 256, 256, 0, s_prep>>>(eidx, etype);

    // main stream: weight convert -> hW GEMM (fp16 out)
    convert_w_kernel<<<((128 + 768) * 32 + 255) / 256, 256>>>(W_msg, W_ih, W_hh);
    mma_gemm<true><<<dim3(GB_TOT, 1), 256, MMA_SMEM>>>(h, nullptr, wh,
                                                       b_msg, hWh, NNODES, 128, 0);
    cudaEventRecord(s_ev_hw, 0);

    // prep stream: aggregate in two halves (needs hW + CSR)
    cudaStreamWaitEvent(s_prep, s_ev_hw, 0);
    aggregate_kernel<<<(NHALF1 * 32 + 255) / 256, 256, 0, s_prep>>>(emb, 0, NHALF1);
    cudaEventRecord(s_ev_a1, s_prep);
    aggregate_kernel<<<(NHALF2 * 32 + 255) / 256, 256, 0, s_prep>>>(emb, NHALF1, NHALF2);
    cudaEventRecord(s_ev_a2, s_prep);

    // main stream: gi GEMM halves (fp16 out), each unblocked by its aggregate half
    cudaStreamWaitEvent(0, s_ev_a1, 0);
    mma_gemm<false><<<dim3(GB1, 3), 256, MMA_SMEM>>>(nullptr, mh, wh + W_IH_OFF,
                                                     b_ih, gih, NNODES, 384, 0);
    cudaEventRecord(s_ev_gi1, 0);
    cudaStreamWaitEvent(0, s_ev_a2, 0);
    mma_gemm<false><<<dim3(GB2, 3), 256, MMA_SMEM>>>(nullptr, mh, wh + W_IH_OFF,
                                                     b_ih, gih, NNODES, 384, GB1);
    cudaEventRecord(s_ev_gi2, 0);

    // prep stream: gh+gates halves, overlapping gi half2 on main
    cudaStreamWaitEvent(s_prep, s_ev_gi1, 0);
    gh_gates_kernel<<<dim3(GB1, 2), 512, GGF_SMEM, s_prep>>>(h, wh + W_HH_OFF,
                                                             b_hh, gih, out, NNODES, 0);
    cudaStreamWaitEvent(s_prep, s_ev_gi2, 0);
    gh_gates_kernel<<<dim3(GB2, 2), 512, GGF_SMEM, s_prep>>>(h, wh + W_HH_OFF,
                                                             b_hh, gih, out, NNODES, GB1);
    cudaEventRecord(s_ev_done, s_prep);

    // join back to origin stream for capture
    cudaStreamWaitEvent(0, s_ev_done, 0);
}

// round 16
// speedup vs baseline: 1.1025x; 1.0130x over previous
#include <cuda_runtime.h>
#include <cuda_fp16.h>
#include <math.h>
#include <stdint.h>

#define H       128
#define NNODES  50000
#define NEDGES  600000
#define NTYPES  9

#define SBLK    512
#define NSB     ((NNODES + SBLK - 1) / SBLK)   // 98

#define PITCH   136                 // fp16 units; 272B rows, ldmatrix-friendly
#define MMA_SMEM ((128*PITCH + 128*PITCH) * 2)    // 69632 B -> 3 CTA/SM
#define GGF_SMEM ((128*PITCH + 192*PITCH) * 2)    // 87040 B -> 2 CTA/SM, 512 thr

#define GB_TOT  ((NNODES + 127) / 128)   // 391
#define GB1     196
#define GB2     (GB_TOT - GB1)           // 195

// ---------------- scratch ----------------
__device__ __half g_hWh[NNODES * H];                  // hW (fp16)
__device__ __half g_gih[NNODES * 3 * H];              // gi (fp16)
__device__ __half g_mh [NNODES * H];                  // msg (fp16)
__device__ __half g_wh [(128 + 384 + 384) * H];       // W_msg | W_ih | W_hh (fp16)
__device__ int    g_deg [NNODES];
__device__ int    g_off [NNODES + 1];
__device__ int    g_cur [NNODES];
__device__ int    g_perm[NEDGES];
__device__ int    g_bsum[NSB];

// ---------------- helpers ----------------
__device__ __forceinline__ uint32_t smem_u32(const void* p) {
    uint32_t a;
    asm("{ .reg .u64 t; cvta.to.shared.u64 t, %1; cvt.u32.u64 %0, t; }"
        : "=r"(a) : "l"(p));
    return a;
}
#define LDSM4(R, addr) \
    asm volatile("ldmatrix.sync.aligned.m8n8.x4.shared.b16 {%0,%1,%2,%3}, [%4];" \
        : "=r"((R)[0]), "=r"((R)[1]), "=r"((R)[2]), "=r"((R)[3]) : "r"(addr))
#define MMA_FP16(D, A, B0, B1) \
    asm volatile("mma.sync.aligned.m16n8k16.row.col.f32.f16.f16.f32 " \
        "{%0,%1,%2,%3}, {%4,%5,%6,%7}, {%8,%9}, {%0,%1,%2,%3};" \
        : "+f"((D)[0]), "+f"((D)[1]), "+f"((D)[2]), "+f"((D)[3]) \
        : "r"((A)[0]), "r"((A)[1]), "r"((A)[2]), "r"((A)[3]), "r"(B0), "r"(B1))

__device__ __forceinline__ uint2 cvt4h(float4 v) {
    __half2 a = __floats2half2_rn(v.x, v.y);
    __half2 b = __floats2half2_rn(v.z, v.w);
    uint2 r;
    r.x = *(uint32_t*)&a;
    r.y = *(uint32_t*)&b;
    return r;
}
__device__ __forceinline__ uint4 cvt8h(const float4* s) {
    uint2 a = cvt4h(s[0]), b = cvt4h(s[1]);
    return make_uint4(a.x, a.y, b.x, b.y);
}

// ---------------- graph prep ----------------
__global__ void zero_deg_kernel() {
    int i = blockIdx.x * blockDim.x + threadIdx.x;
    if (i < NNODES) g_deg[i] = 0;
}
__global__ void count_kernel(const int* __restrict__ edge_index) {
    int e = blockIdx.x * blockDim.x + threadIdx.x;
    if (e < NEDGES) atomicAdd(&g_deg[edge_index[NEDGES + e]], 1);
}
__global__ void scan1_kernel() {
    int tid = threadIdx.x;
    int i = blockIdx.x * SBLK + tid;
    int v = (i < NNODES) ? g_deg[i] : 0;
    #pragma unroll
    for (int o = 16; o > 0; o >>= 1) v += __shfl_down_sync(0xffffffffu, v, o);
    __shared__ int ws[SBLK / 32];
    if ((tid & 31) == 0) ws[tid >> 5] = v;
    __syncthreads();
    if (tid < 32) {
        int s = (tid < SBLK / 32) ? ws[tid] : 0;
        #pragma unroll
        for (int o = 16; o > 0; o >>= 1) s += __shfl_down_sync(0xffffffffu, s, o);
        if (tid == 0) g_bsum[blockIdx.x] = s;
    }
}
// scan3: block-local exclusive scan + INLINE prefix over g_bsum (scan2 merged)
__global__ void scan3_kernel() {
    __shared__ int ws2[4];
    __shared__ int sbpre;
    __shared__ int wsum[SBLK / 32];
    int tid = threadIdx.x;
    int i = blockIdx.x * SBLK + tid;
    int v = (i < NNODES) ? g_deg[i] : 0;

    // inline exclusive prefix of g_bsum[0..blockIdx.x) (NSB=98 <= 128 threads)
    if (tid < 128) {
        int b = (tid < blockIdx.x) ? g_bsum[tid] : 0;
        #pragma unroll
        for (int o = 16; o > 0; o >>= 1) b += __shfl_down_sync(0xffffffffu, b, o);
        if ((tid & 31) == 0) ws2[tid >> 5] = b;
    }
    __syncthreads();
    if (tid == 0) sbpre = ws2[0] + ws2[1] + ws2[2] + ws2[3];

    // block-local inclusive scan
    int lane = tid & 31, wid = tid >> 5;
    int x = v;
    #pragma unroll
    for (int o = 1; o < 32; o <<= 1) {
        int y = __shfl_up_sync(0xffffffffu, x, o);
        if (lane >= o) x += y;
    }
    if (lane == 31) wsum[wid] = x;
    __syncthreads();
    if (wid == 0) {
        int w = (lane < SBLK / 32) ? wsum[lane] : 0;
        #pragma unroll
        for (int o = 1; o < SBLK / 32; o <<= 1) {
            int y = __shfl_up_sync(0xffffffffu, w, o);
            if (lane >= o) w += y;
        }
        if (lane < SBLK / 32) wsum[lane] = w;
    }
    __syncthreads();
    int excl = x - v + (wid > 0 ? wsum[wid - 1] : 0) + sbpre;
    if (i < NNODES) { g_off[i] = excl; g_cur[i] = excl; }
    if (i == NNODES - 1) g_off[NNODES] = excl + v;
}
__global__ void scatter_kernel(const int* __restrict__ edge_index,
                               const int* __restrict__ etype) {
    int e = blockIdx.x * blockDim.x + threadIdx.x;
    if (e < NEDGES) {
        int d = edge_index[NEDGES + e];
        int s = edge_index[e];
        int t = etype[e];
        t = min(max(t, 0), NTYPES - 1);
        int pos = atomicAdd(&g_cur[d], 1);
        g_perm[pos] = (s << 4) | t;
    }
}

// ---------------- weight convert (fp32 -> fp16, one plane) -------------------
__global__ void convert_w_kernel(const float* __restrict__ Wm,
                                 const float* __restrict__ Wi,
                                 const float* __restrict__ Wh) {
    int i = blockIdx.x * blockDim.x + threadIdx.x;
    const int S1 = 128 * 32, S2 = (128 + 384) * 32, S3 = (128 + 768) * 32;
    if (i >= S3) return;
    float4 v;
    if (i < S1)       v = ((const float4*)Wm)[i];
    else if (i < S2)  v = ((const float4*)Wi)[i - S1];
    else              v = ((const float4*)Wh)[i - S2];
    ((uint2*)g_wh)[i] = cvt4h(v);
}

// ---------------- aggregate: warp per node, fp16 gather, MLP=4 ---------------
__global__ void aggregate_kernel(const float* __restrict__ emb) {
    int node = (blockIdx.x * blockDim.x + threadIdx.x) >> 5;
    int lane = threadIdx.x & 31;
    if (node >= NNODES) return;
    int s0 = g_off[node];
    int s1 = g_off[node + 1];
    float4 acc = make_float4(0.f, 0.f, 0.f, 0.f);
    int i = s0;
    for (; i + 4 <= s1; i += 4) {
        int p0 = g_perm[i],     p1 = g_perm[i + 1];
        int p2 = g_perm[i + 2], p3 = g_perm[i + 3];
        uint2 u0 = *((const uint2*)(g_hWh + (size_t)(p0 >> 4) * H) + lane);
        uint2 u1 = *((const uint2*)(g_hWh + (size_t)(p1 >> 4) * H) + lane);
        uint2 u2 = *((const uint2*)(g_hWh + (size_t)(p2 >> 4) * H) + lane);
        uint2 u3 = *((const uint2*)(g_hWh + (size_t)(p3 >> 4) * H) + lane);
        float4 e0 = *((const float4*)(emb + (size_t)(p0 & 15) * H) + lane);
        float4 e1 = *((const float4*)(emb + (size_t)(p1 & 15) * H) + lane);
        float4 e2 = *((const float4*)(emb + (size_t)(p2 & 15) * H) + lane);
        float4 e3 = *((const float4*)(emb + (size_t)(p3 & 15) * H) + lane);
        float2 a0 = __half22float2(*(__half2*)&u0.x), a1 = __half22float2(*(__half2*)&u0.y);
        float2 b0 = __half22float2(*(__half2*)&u1.x), b1 = __half22float2(*(__half2*)&u1.y);
        float2 c0 = __half22float2(*(__half2*)&u2.x), c1 = __half22float2(*(__half2*)&u2.y);
        float2 d0 = __half22float2(*(__half2*)&u3.x), d1 = __half22float2(*(__half2*)&u3.y);
        acc.x += (a0.x + e0.x) + (b0.x + e1.x) + (c0.x + e2.x) + (d0.x + e3.x);
        acc.y += (a0.y + e0.y) + (b0.y + e1.y) + (c0.y + e2.y) + (d0.y + e3.y);
        acc.z += (a1.x + e0.z) + (b1.x + e1.z) + (c1.x + e2.z) + (d1.x + e3.z);
        acc.w += (a1.y + e0.w) + (b1.y + e1.w) + (c1.y + e2.w) + (d1.y + e3.w);
    }
    for (; i < s1; i++) {
        int p = g_perm[i];
        uint2 u = *((const uint2*)(g_hWh + (size_t)(p >> 4) * H) + lane);
        float2 f0 = __half22float2(*(__half2*)&u.x);
        float2 f1 = __half22float2(*(__half2*)&u.y);
        float4 ev = *((const float4*)(emb + (size_t)(p & 15) * H) + lane);
        acc.x += f0.x + ev.x;  acc.y += f0.y + ev.y;
        acc.z += f1.x + ev.z;  acc.w += f1.y + ev.w;
    }
    ((uint2*)(g_mh + (size_t)node * H))[lane] = cvt4h(acc);
}

// ---------------- fp16 1-pass GEMM, 128x128 block tile, fp16 output ----------
template <bool F32A>
__global__ __launch_bounds__(256)
void mma_gemm(const float* __restrict__ Afp, const __half* __restrict__ Ah,
              const __half* __restrict__ Bh,
              const float* __restrict__ bias, __half* __restrict__ C,
              int M, int N, int mblk_off) {
    extern __shared__ __half smh[];
    __half* sA = smh;                 // [128][PITCH]
    __half* sB = smh + 128 * PITCH;   // [128][PITCH]

    const int tid = threadIdx.x;
    const int m0 = (blockIdx.x + mblk_off) * 128;
    const int n0 = blockIdx.y * 128;

    for (int i = tid; i < 128 * 16; i += 256) {
        int r = i >> 4, c = i & 15;
        int gr = m0 + r;
        uint4 vh = make_uint4(0, 0, 0, 0);
        if (gr < M) {
            if (F32A) vh = cvt8h((const float4*)(Afp + (size_t)gr * H + c * 8));
            else      vh = *(const uint4*)(Ah + (size_t)gr * H + c * 8);
        }
        *(uint4*)(sA + r * PITCH + c * 8) = vh;
        int gn = n0 + r;
        *(uint4*)(sB + r * PITCH + c * 8) = *(const uint4*)(Bh + (size_t)gn * H + c * 8);
    }
    __syncthreads();

    const int lane = tid & 31;
    const int w = tid >> 5;
    const int wm = (w & 3) * 32;
    const int wn = (w >> 2) * 64;

    float d[2][8][4];
    #pragma unroll
    for (int mt = 0; mt < 2; mt++)
        #pragma unroll
        for (int nt = 0; nt < 8; nt++)
            #pragma unroll
            for (int q = 0; q < 4; q++) d[mt][nt][q] = 0.f;

    const uint32_t sbase = smem_u32(smh);
    const int t8 = lane >> 3, r8 = lane & 7;
    uint32_t aA[2];
    #pragma unroll
    for (int mt = 0; mt < 2; mt++) {
        int row = wm + mt * 16 + (t8 & 1) * 8 + r8;
        aA[mt] = sbase + (uint32_t)(row * PITCH + (t8 >> 1) * 8) * 2;
    }
    uint32_t aB[4];
    #pragma unroll
    for (int g = 0; g < 4; g++) {
        int row = wn + g * 16 + (t8 >> 1) * 8 + r8;
        aB[g] = sbase + 128 * PITCH * 2 + (uint32_t)(row * PITCH + (t8 & 1) * 8) * 2;
    }

    #pragma unroll
    for (int kk = 0; kk < 8; kk++) {
        const uint32_t ko = kk * 32;
        uint32_t a[2][4], b[4][4];
        #pragma unroll
        for (int mt = 0; mt < 2; mt++) LDSM4(a[mt], aA[mt] + ko);
        #pragma unroll
        for (int g = 0; g < 4; g++)   LDSM4(b[g], aB[g] + ko);
        #pragma unroll
        for (int mt = 0; mt < 2; mt++)
            #pragma unroll
            for (int nt = 0; nt < 8; nt++) {
                int g = nt >> 1, o = (nt & 1) * 2;
                MMA_FP16(d[mt][nt], a[mt], b[g][o], b[g][o + 1]);
            }
    }

    const int rr = lane >> 2, c2 = (lane & 3) * 2;
    #pragma unroll
    for (int mt = 0; mt < 2; mt++)
        #pragma unroll
        for (int nt = 0; nt < 8; nt++) {
            int col = n0 + wn + nt * 8 + c2;
            float b0 = bias[col], b1 = bias[col + 1];
            int row0 = m0 + wm + mt * 16 + rr;
            if (row0 < M) {
                __half2 hv = __floats2half2_rn(d[mt][nt][0] + b0, d[mt][nt][1] + b1);
                *(uint32_t*)(C + (size_t)row0 * N + col) = *(uint32_t*)&hv;
            }
            int row1 = row0 + 8;
            if (row1 < M) {
                __half2 hv = __floats2half2_rn(d[mt][nt][2] + b0, d[mt][nt][3] + b1);
                *(uint32_t*)(C + (size_t)row1 * N + col) = *(uint32_t*)&hv;
            }
        }
}

// ---------------- fused gh GEMM + GRU gates (round-13 config) ----------------
__global__ __launch_bounds__(512)
void gh_gates_kernel(const float* __restrict__ h,
                     const __half* __restrict__ Bh,
                     const float* __restrict__ b_hh,
                     const __half* __restrict__ gi,
                     float* __restrict__ out, int M, int mblk_off) {
    extern __shared__ __half smh[];
    __half* sB = smh + 128 * PITCH;   // [192][PITCH]

    const int tid = threadIdx.x;
    const int m0 = (blockIdx.x + mblk_off) * 128;
    const int c0 = blockIdx.y * 64;

    for (int i = tid; i < 128 * 16; i += 512) {
        int r = i >> 4, c = i & 15;
        int gr = m0 + r;
        uint4 vh = make_uint4(0, 0, 0, 0);
        if (gr < M) vh = cvt8h((const float4*)(h + (size_t)gr * H + c * 8));
        *(uint4*)(smh + r * PITCH + c * 8) = vh;
    }
    for (int i = tid; i < 192 * 16; i += 512) {
        int r = i >> 4, c = i & 15;
        int s = r >> 6, rl = r & 63;
        int grow = s * 128 + c0 + rl;
        *(uint4*)(sB + r * PITCH + c * 8) = *(const uint4*)(Bh + (size_t)grow * H + c * 8);
    }
    __syncthreads();

    const int lane = tid & 31;
    const int w = tid >> 5;
    const int wm = (w & 3) * 32;       // 4 m-groups
    const int wn = (w >> 2) * 16;      // 4 n-groups of 16 cols

    float d[3][2][2][4];
    #pragma unroll
    for (int s = 0; s < 3; s++)
        #pragma unroll
        for (int mt = 0; mt < 2; mt++)
            #pragma unroll
            for (int nt = 0; nt < 2; nt++)
                #pragma unroll
                for (int q = 0; q < 4; q++) d[s][mt][nt][q] = 0.f;

    const uint32_t sbase = smem_u32(smh);
    const int t8 = lane >> 3, r8 = lane & 7;
    uint32_t aA[2];
    #pragma unroll
    for (int mt = 0; mt < 2; mt++) {
        int row = wm + mt * 16 + (t8 & 1) * 8 + r8;
        aA[mt] = sbase + (uint32_t)(row * PITCH + (t8 >> 1) * 8) * 2;
    }
    const uint32_t Bbase = sbase + 128 * PITCH * 2;
    uint32_t aB[3];
    #pragma unroll
    for (int s = 0; s < 3; s++) {
        int row = s * 64 + wn + (t8 >> 1) * 8 + r8;
        aB[s] = Bbase + (uint32_t)(row * PITCH + (t8 & 1) * 8) * 2;
    }

    #pragma unroll
    for (int kk = 0; kk < 8; kk++) {
        const uint32_t ko = kk * 32;
        uint32_t a[2][4];
        #pragma unroll
        for (int mt = 0; mt < 2; mt++) LDSM4(a[mt], aA[mt] + ko);
        #pragma unroll
        for (int s = 0; s < 3; s++) {
            uint32_t b[4];
            LDSM4(b, aB[s] + ko);
            #pragma unroll
            for (int mt = 0; mt < 2; mt++)
                #pragma unroll
                for (int nt = 0; nt < 2; nt++) {
                    int o = nt * 2;
                    MMA_FP16(d[s][mt][nt], a[mt], b[o], b[o + 1]);
                }
        }
    }

    const int rr = lane >> 2, c2 = (lane & 3) * 2;
    #pragma unroll
    for (int mt = 0; mt < 2; mt++)
        #pragma unroll
        for (int nt = 0; nt < 2; nt++) {
            int col = c0 + wn + nt * 8 + c2;
            float bhr0 = b_hh[col],       bhr1 = b_hh[col + 1];
            float bhz0 = b_hh[128 + col], bhz1 = b_hh[128 + col + 1];
            float bhn0 = b_hh[256 + col], bhn1 = b_hh[256 + col + 1];
            #pragma unroll
            for (int half = 0; half < 2; half++) {
                int row = m0 + wm + mt * 16 + rr + half * 8;
                if (row >= M) continue;
                size_t gb = (size_t)row * 384 + col;
                float2 gir = __half22float2(*(const __half2*)(gi + gb));
                float2 giz = __half22float2(*(const __half2*)(gi + gb + 128));
                float2 gin = __half22float2(*(const __half2*)(gi + gb + 256));
                float ghr0 = d[0][mt][nt][half * 2]     + bhr0;
                float ghr1 = d[0][mt][nt][half * 2 + 1] + bhr1;
                float ghz0 = d[1][mt][nt][half * 2]     + bhz0;
                float ghz1 = d[1][mt][nt][half * 2 + 1] + bhz1;
                float ghn0 = d[2][mt][nt][half * 2]     + bhn0;
                float ghn1 = d[2][mt][nt][half * 2 + 1] + bhn1;
                float r0 = 1.f / (1.f + __expf(-(gir.x + ghr0)));
                float r1 = 1.f / (1.f + __expf(-(gir.y + ghr1)));
                float z0 = 1.f / (1.f + __expf(-(giz.x + ghz0)));
                float z1 = 1.f / (1.f + __expf(-(giz.y + ghz1)));
                float n0v = tanhf(gin.x + r0 * ghn0);
                float n1v = tanhf(gin.y + r1 * ghn1);
                float2 hv = *(const float2*)(h + (size_t)row * H + col);
                float2 o;
                o.x = (1.f - z0) * n0v + z0 * hv.x;
                o.y = (1.f - z1) * n1v + z1 * hv.y;
                *(float2*)(out + (size_t)row * H + col) = o;
            }
        }
}

// ---------------- launch ----------------
static cudaStream_t s_prep = 0;
static cudaEvent_t  s_ev_fork = 0, s_ev_hw = 0, s_ev_agg = 0;
static cudaEvent_t  s_ev_gi1 = 0, s_ev_gi2 = 0, s_ev_done = 0;

extern "C" void kernel_launch(void* const* d_in, const int* in_sizes, int n_in,
                              void* d_out, int out_size) {
    const float* h     = (const float*)d_in[0];
    const int*   eidx  = (const int*)  d_in[1];
    const int*   etype = (const int*)  d_in[2];
    const float* W_msg = (const float*)d_in[4];
    const float* b_msg = (const float*)d_in[5];
    const float* emb   = (const float*)d_in[6];
    const float* W_ih  = (const float*)d_in[7];
    const float* W_hh  = (const float*)d_in[8];
    const float* b_ih  = (const float*)d_in[9];
    const float* b_hh  = (const float*)d_in[10];
    float* out = (float*)d_out;

    if (s_prep == 0) {
        cudaStreamCreateWithFlags(&s_prep, cudaStreamNonBlocking);
        cudaEventCreateWithFlags(&s_ev_fork, cudaEventDisableTiming);
        cudaEventCreateWithFlags(&s_ev_hw,   cudaEventDisableTiming);
        cudaEventCreateWithFlags(&s_ev_agg,  cudaEventDisableTiming);
        cudaEventCreateWithFlags(&s_ev_gi1,  cudaEventDisableTiming);
        cudaEventCreateWithFlags(&s_ev_gi2,  cudaEventDisableTiming);
        cudaEventCreateWithFlags(&s_ev_done, cudaEventDisableTiming);
    }

    __half *hWh, *gih, *mh, *wh;
    cudaGetSymbolAddress((void**)&hWh, g_hWh);
    cudaGetSymbolAddress((void**)&gih, g_gih);
    cudaGetSymbolAddress((void**)&mh,  g_mh);
    cudaGetSymbolAddress((void**)&wh,  g_wh);

    cudaFuncSetAttribute(mma_gemm<true>,  cudaFuncAttributeMaxDynamicSharedMemorySize, MMA_SMEM);
    cudaFuncSetAttribute(mma_gemm<false>, cudaFuncAttributeMaxDynamicSharedMemorySize, MMA_SMEM);
    cudaFuncSetAttribute(gh_gates_kernel, cudaFuncAttributeMaxDynamicSharedMemorySize, GGF_SMEM);

    const int W_IH_OFF = 128 * H;
    const int W_HH_OFF = (128 + 384) * H;

    // fork
    cudaEventRecord(s_ev_fork, 0);
    cudaStreamWaitEvent(s_prep, s_ev_fork, 0);

    // prep stream: CSR build (scan2 merged into scan3)
    zero_deg_kernel<<<(NNODES + 255) / 256, 256, 0, s_prep>>>();
    count_kernel  <<<(NEDGES + 255) / 256, 256, 0, s_prep>>>(eidx);
    scan1_kernel<<<NSB, SBLK, 0, s_prep>>>();
    scan3_kernel<<<NSB, SBLK, 0, s_prep>>>();
    scatter_kernel<<<(NEDGES + 255) / 256, 256, 0, s_prep>>>(eidx, etype);

    // main stream: weight convert -> hW GEMM (fp16 out)
    convert_w_kernel<<<((128 + 768) * 32 + 255) / 256, 256>>>(W_msg, W_ih, W_hh);
    mma_gemm<true><<<dim3(GB_TOT, 1), 256, MMA_SMEM>>>(h, nullptr, wh,
                                                       b_msg, hWh, NNODES, 128, 0);
    cudaEventRecord(s_ev_hw, 0);

    // prep stream: single aggregate (needs hW + CSR)
    cudaStreamWaitEvent(s_prep, s_ev_hw, 0);
    aggregate_kernel<<<(NNODES * 32 + 255) / 256, 256, 0, s_prep>>>(emb);
    cudaEventRecord(s_ev_agg, s_prep);

    // main stream: gi GEMM halves (fp16 out)
    cudaStreamWaitEvent(0, s_ev_agg, 0);
    mma_gemm<false><<<dim3(GB1, 3), 256, MMA_SMEM>>>(nullptr, mh, wh + W_IH_OFF,
                                                     b_ih, gih, NNODES, 384, 0);
    cudaEventRecord(s_ev_gi1, 0);
    mma_gemm<false><<<dim3(GB2, 3), 256, MMA_SMEM>>>(nullptr, mh, wh + W_IH_OFF,
                                                     b_ih, gih, NNODES, 384, GB1);
    cudaEventRecord(s_ev_gi2, 0);

    // prep stream: gh+gates halves, overlapping gi half2 on main
    cudaStreamWaitEvent(s_prep, s_ev_gi1, 0);
    gh_gates_kernel<<<dim3(GB1, 2), 512, GGF_SMEM, s_prep>>>(h, wh + W_HH_OFF,
                                                             b_hh, gih, out, NNODES, 0);
    cudaStreamWaitEvent(s_prep, s_ev_gi2, 0);
    gh_gates_kernel<<<dim3(GB2, 2), 512, GGF_SMEM, s_prep>>>(h, wh + W_HH_OFF,
                                                             b_hh, gih, out, NNODES, GB1);
    cudaEventRecord(s_ev_done, s_prep);

    // join back to origin stream for capture
    cudaStreamWaitEvent(0, s_ev_done, 0);
}

// round 17
// speedup vs baseline: 1.1027x; 1.0002x over previous
#include <cuda_runtime.h>
#include <cuda_fp16.h>
#include <math.h>
#include <stdint.h>

#define H       128
#define NNODES  50000
#define NEDGES  600000
#define NTYPES  9

#define SBLK    512
#define NSB     ((NNODES + SBLK - 1) / SBLK)   // 98

#define PITCH   136                 // fp16 units; 272B rows, ldmatrix-friendly
#define MMA_SMEM ((128*PITCH + 128*PITCH) * 2)    // 69632 B -> 3 CTA/SM
#define GGF_SMEM ((128*PITCH + 192*PITCH) * 2)    // 87040 B -> 2 CTA/SM, 512 thr

#define GB_TOT  ((NNODES + 127) / 128)   // 391
#define GB1     196
#define GB2     (GB_TOT - GB1)           // 195

// ---------------- scratch ----------------
// NOTE: g_deg relies on zero-initialization at module load + the self-cleaning
// invariant: scan3 (its last reader) re-zeros every element it consumes, so
// every execution of the graph starts AND ends with g_deg == 0.
__device__ __half g_hWh[NNODES * H];                  // hW (fp16)
__device__ __half g_gih[NNODES * 3 * H];              // gi (fp16)
__device__ __half g_mh [NNODES * H];                  // msg (fp16)
__device__ __half g_wh [(128 + 384 + 384) * H];       // W_msg | W_ih | W_hh (fp16)
__device__ int    g_deg [NNODES];                     // zero-init; self-cleaning
__device__ int    g_off [NNODES + 1];
__device__ int    g_cur [NNODES];
__device__ int    g_perm[NEDGES];
__device__ int    g_bsum[NSB];

// ---------------- helpers ----------------
__device__ __forceinline__ uint32_t smem_u32(const void* p) {
    uint32_t a;
    asm("{ .reg .u64 t; cvta.to.shared.u64 t, %1; cvt.u32.u64 %0, t; }"
        : "=r"(a) : "l"(p));
    return a;
}
#define LDSM4(R, addr) \
    asm volatile("ldmatrix.sync.aligned.m8n8.x4.shared.b16 {%0,%1,%2,%3}, [%4];" \
        : "=r"((R)[0]), "=r"((R)[1]), "=r"((R)[2]), "=r"((R)[3]) : "r"(addr))
#define MMA_FP16(D, A, B0, B1) \
    asm volatile("mma.sync.aligned.m16n8k16.row.col.f32.f16.f16.f32 " \
        "{%0,%1,%2,%3}, {%4,%5,%6,%7}, {%8,%9}, {%0,%1,%2,%3};" \
        : "+f"((D)[0]), "+f"((D)[1]), "+f"((D)[2]), "+f"((D)[3]) \
        : "r"((A)[0]), "r"((A)[1]), "r"((A)[2]), "r"((A)[3]), "r"(B0), "r"(B1))

__device__ __forceinline__ uint2 cvt4h(float4 v) {
    __half2 a = __floats2half2_rn(v.x, v.y);
    __half2 b = __floats2half2_rn(v.z, v.w);
    uint2 r;
    r.x = *(uint32_t*)&a;
    r.y = *(uint32_t*)&b;
    return r;
}
__device__ __forceinline__ uint4 cvt8h(const float4* s) {
    uint2 a = cvt4h(s[0]), b = cvt4h(s[1]);
    return make_uint4(a.x, a.y, b.x, b.y);
}

// ---------------- graph prep ----------------
__global__ void count_kernel(const int* __restrict__ edge_index) {
    int e = blockIdx.x * blockDim.x + threadIdx.x;
    if (e < NEDGES) atomicAdd(&g_deg[edge_index[NEDGES + e]], 1);
}
__global__ void scan1_kernel() {
    int tid = threadIdx.x;
    int i = blockIdx.x * SBLK + tid;
    int v = (i < NNODES) ? g_deg[i] : 0;
    #pragma unroll
    for (int o = 16; o > 0; o >>= 1) v += __shfl_down_sync(0xffffffffu, v, o);
    __shared__ int ws[SBLK / 32];
    if ((tid & 31) == 0) ws[tid >> 5] = v;
    __syncthreads();
    if (tid < 32) {
        int s = (tid < SBLK / 32) ? ws[tid] : 0;
        #pragma unroll
        for (int o = 16; o > 0; o >>= 1) s += __shfl_down_sync(0xffffffffu, s, o);
        if (tid == 0) g_bsum[blockIdx.x] = s;
    }
}
// scan3: block-local exclusive scan + inline prefix over g_bsum; also
// re-zeros g_deg (last reader) to maintain the zero-on-entry invariant.
__global__ void scan3_kernel() {
    __shared__ int ws2[4];
    __shared__ int sbpre;
    __shared__ int wsum[SBLK / 32];
    int tid = threadIdx.x;
    int i = blockIdx.x * SBLK + tid;
    int v = (i < NNODES) ? g_deg[i] : 0;

    // inline exclusive prefix of g_bsum[0..blockIdx.x) (NSB=98 <= 128 threads)
    if (tid < 128) {
        int b = (tid < blockIdx.x) ? g_bsum[tid] : 0;
        #pragma unroll
        for (int o = 16; o > 0; o >>= 1) b += __shfl_down_sync(0xffffffffu, b, o);
        if ((tid & 31) == 0) ws2[tid >> 5] = b;
    }
    __syncthreads();
    if (tid == 0) sbpre = ws2[0] + ws2[1] + ws2[2] + ws2[3];

    // block-local inclusive scan
    int lane = tid & 31, wid = tid >> 5;
    int x = v;
    #pragma unroll
    for (int o = 1; o < 32; o <<= 1) {
        int y = __shfl_up_sync(0xffffffffu, x, o);
        if (lane >= o) x += y;
    }
    if (lane == 31) wsum[wid] = x;
    __syncthreads();
    if (wid == 0) {
        int w = (lane < SBLK / 32) ? wsum[lane] : 0;
        #pragma unroll
        for (int o = 1; o < SBLK / 32; o <<= 1) {
            int y = __shfl_up_sync(0xffffffffu, w, o);
            if (lane >= o) w += y;
        }
        if (lane < SBLK / 32) wsum[lane] = w;
    }
    __syncthreads();
    int excl = x - v + (wid > 0 ? wsum[wid - 1] : 0) + sbpre;
    if (i < NNODES) {
        g_off[i] = excl;
        g_cur[i] = excl;
        g_deg[i] = 0;              // self-clean for next execution
    }
    if (i == NNODES - 1) g_off[NNODES] = excl + v;
}
__global__ void scatter_kernel(const int* __restrict__ edge_index,
                               const int* __restrict__ etype) {
    int e = blockIdx.x * blockDim.x + threadIdx.x;
    if (e < NEDGES) {
        int d = edge_index[NEDGES + e];
        int s = edge_index[e];
        int t = etype[e];
        t = min(max(t, 0), NTYPES - 1);
        int pos = atomicAdd(&g_cur[d], 1);
        g_perm[pos] = (s << 4) | t;
    }
}

// ---------------- weight convert (fp32 -> fp16, one plane) -------------------
__global__ void convert_w_kernel(const float* __restrict__ Wm,
                                 const float* __restrict__ Wi,
                                 const float* __restrict__ Wh) {
    int i = blockIdx.x * blockDim.x + threadIdx.x;
    const int S1 = 128 * 32, S2 = (128 + 384) * 32, S3 = (128 + 768) * 32;
    if (i >= S3) return;
    float4 v;
    if (i < S1)       v = ((const float4*)Wm)[i];
    else if (i < S2)  v = ((const float4*)Wi)[i - S1];
    else              v = ((const float4*)Wh)[i - S2];
    ((uint2*)g_wh)[i] = cvt4h(v);
}

// ---------------- aggregate: warp per node, fp16 gather, MLP=4 ---------------
__global__ void aggregate_kernel(const float* __restrict__ emb) {
    int node = (blockIdx.x * blockDim.x + threadIdx.x) >> 5;
    int lane = threadIdx.x & 31;
    if (node >= NNODES) return;
    int s0 = g_off[node];
    int s1 = g_off[node + 1];
    float4 acc = make_float4(0.f, 0.f, 0.f, 0.f);
    int i = s0;
    for (; i + 4 <= s1; i += 4) {
        int p0 = g_perm[i],     p1 = g_perm[i + 1];
        int p2 = g_perm[i + 2], p3 = g_perm[i + 3];
        uint2 u0 = *((const uint2*)(g_hWh + (size_t)(p0 >> 4) * H) + lane);
        uint2 u1 = *((const uint2*)(g_hWh + (size_t)(p1 >> 4) * H) + lane);
        uint2 u2 = *((const uint2*)(g_hWh + (size_t)(p2 >> 4) * H) + lane);
        uint2 u3 = *((const uint2*)(g_hWh + (size_t)(p3 >> 4) * H) + lane);
        float4 e0 = *((const float4*)(emb + (size_t)(p0 & 15) * H) + lane);
        float4 e1 = *((const float4*)(emb + (size_t)(p1 & 15) * H) + lane);
        float4 e2 = *((const float4*)(emb + (size_t)(p2 & 15) * H) + lane);
        float4 e3 = *((const float4*)(emb + (size_t)(p3 & 15) * H) + lane);
        float2 a0 = __half22float2(*(__half2*)&u0.x), a1 = __half22float2(*(__half2*)&u0.y);
        float2 b0 = __half22float2(*(__half2*)&u1.x), b1 = __half22float2(*(__half2*)&u1.y);
        float2 c0 = __half22float2(*(__half2*)&u2.x), c1 = __half22float2(*(__half2*)&u2.y);
        float2 d0 = __half22float2(*(__half2*)&u3.x), d1 = __half22float2(*(__half2*)&u3.y);
        acc.x += (a0.x + e0.x) + (b0.x + e1.x) + (c0.x + e2.x) + (d0.x + e3.x);
        acc.y += (a0.y + e0.y) + (b0.y + e1.y) + (c0.y + e2.y) + (d0.y + e3.y);
        acc.z += (a1.x + e0.z) + (b1.x + e1.z) + (c1.x + e2.z) + (d1.x + e3.z);
        acc.w += (a1.y + e0.w) + (b1.y + e1.w) + (c1.y + e2.w) + (d1.y + e3.w);
    }
    for (; i < s1; i++) {
        int p = g_perm[i];
        uint2 u = *((const uint2*)(g_hWh + (size_t)(p >> 4) * H) + lane);
        float2 f0 = __half22float2(*(__half2*)&u.x);
        float2 f1 = __half22float2(*(__half2*)&u.y);
        float4 ev = *((const float4*)(emb + (size_t)(p & 15) * H) + lane);
        acc.x += f0.x + ev.x;  acc.y += f0.y + ev.y;
        acc.z += f1.x + ev.z;  acc.w += f1.y + ev.w;
    }
    ((uint2*)(g_mh + (size_t)node * H))[lane] = cvt4h(acc);
}

// ---------------- fp16 1-pass GEMM, 128x128 block tile, fp16 output ----------
template <bool F32A>
__global__ __launch_bounds__(256)
void mma_gemm(const float* __restrict__ Afp, const __half* __restrict__ Ah,
              const __half* __restrict__ Bh,
              const float* __restrict__ bias, __half* __restrict__ C,
              int M, int N, int mblk_off) {
    extern __shared__ __half smh[];
    __half* sA = smh;                 // [128][PITCH]
    __half* sB = smh + 128 * PITCH;   // [128][PITCH]

    const int tid = threadIdx.x;
    const int m0 = (blockIdx.x + mblk_off) * 128;
    const int n0 = blockIdx.y * 128;

    for (int i = tid; i < 128 * 16; i += 256) {
        int r = i >> 4, c = i & 15;
        int gr = m0 + r;
        uint4 vh = make_uint4(0, 0, 0, 0);
        if (gr < M) {
            if (F32A) vh = cvt8h((const float4*)(Afp + (size_t)gr * H + c * 8));
            else      vh = *(const uint4*)(Ah + (size_t)gr * H + c * 8);
        }
        *(uint4*)(sA + r * PITCH + c * 8) = vh;
        int gn = n0 + r;
        *(uint4*)(sB + r * PITCH + c * 8) = *(const uint4*)(Bh + (size_t)gn * H + c * 8);
    }
    __syncthreads();

    const int lane = tid & 31;
    const int w = tid >> 5;
    const int wm = (w & 3) * 32;
    const int wn = (w >> 2) * 64;

    float d[2][8][4];
    #pragma unroll
    for (int mt = 0; mt < 2; mt++)
        #pragma unroll
        for (int nt = 0; nt < 8; nt++)
            #pragma unroll
            for (int q = 0; q < 4; q++) d[mt][nt][q] = 0.f;

    const uint32_t sbase = smem_u32(smh);
    const int t8 = lane >> 3, r8 = lane & 7;
    uint32_t aA[2];
    #pragma unroll
    for (int mt = 0; mt < 2; mt++) {
        int row = wm + mt * 16 + (t8 & 1) * 8 + r8;
        aA[mt] = sbase + (uint32_t)(row * PITCH + (t8 >> 1) * 8) * 2;
    }
    uint32_t aB[4];
    #pragma unroll
    for (int g = 0; g < 4; g++) {
        int row = wn + g * 16 + (t8 >> 1) * 8 + r8;
        aB[g] = sbase + 128 * PITCH * 2 + (uint32_t)(row * PITCH + (t8 & 1) * 8) * 2;
    }

    #pragma unroll
    for (int kk = 0; kk < 8; kk++) {
        const uint32_t ko = kk * 32;
        uint32_t a[2][4], b[4][4];
        #pragma unroll
        for (int mt = 0; mt < 2; mt++) LDSM4(a[mt], aA[mt] + ko);
        #pragma unroll
        for (int g = 0; g < 4; g++)   LDSM4(b[g], aB[g] + ko);
        #pragma unroll
        for (int mt = 0; mt < 2; mt++)
            #pragma unroll
            for (int nt = 0; nt < 8; nt++) {
                int g = nt >> 1, o = (nt & 1) * 2;
                MMA_FP16(d[mt][nt], a[mt], b[g][o], b[g][o + 1]);
            }
    }

    const int rr = lane >> 2, c2 = (lane & 3) * 2;
    #pragma unroll
    for (int mt = 0; mt < 2; mt++)
        #pragma unroll
        for (int nt = 0; nt < 8; nt++) {
            int col = n0 + wn + nt * 8 + c2;
            float b0 = bias[col], b1 = bias[col + 1];
            int row0 = m0 + wm + mt * 16 + rr;
            if (row0 < M) {
                __half2 hv = __floats2half2_rn(d[mt][nt][0] + b0, d[mt][nt][1] + b1);
                *(uint32_t*)(C + (size_t)row0 * N + col) = *(uint32_t*)&hv;
            }
            int row1 = row0 + 8;
            if (row1 < M) {
                __half2 hv = __floats2half2_rn(d[mt][nt][2] + b0, d[mt][nt][3] + b1);
                *(uint32_t*)(C + (size_t)row1 * N + col) = *(uint32_t*)&hv;
            }
        }
}

// ---------------- fused gh GEMM + GRU gates (round-13 config) ----------------
__global__ __launch_bounds__(512)
void gh_gates_kernel(const float* __restrict__ h,
                     const __half* __restrict__ Bh,
                     const float* __restrict__ b_hh,
                     const __half* __restrict__ gi,
                     float* __restrict__ out, int M, int mblk_off) {
    extern __shared__ __half smh[];
    __half* sB = smh + 128 * PITCH;   // [192][PITCH]

    const int tid = threadIdx.x;
    const int m0 = (blockIdx.x + mblk_off) * 128;
    const int c0 = blockIdx.y * 64;

    for (int i = tid; i < 128 * 16; i += 512) {
        int r = i >> 4, c = i & 15;
        int gr = m0 + r;
        uint4 vh = make_uint4(0, 0, 0, 0);
        if (gr < M) vh = cvt8h((const float4*)(h + (size_t)gr * H + c * 8));
        *(uint4*)(smh + r * PITCH + c * 8) = vh;
    }
    for (int i = tid; i < 192 * 16; i += 512) {
        int r = i >> 4, c = i & 15;
        int s = r >> 6, rl = r & 63;
        int grow = s * 128 + c0 + rl;
        *(uint4*)(sB + r * PITCH + c * 8) = *(const uint4*)(Bh + (size_t)grow * H + c * 8);
    }
    __syncthreads();

    const int lane = tid & 31;
    const int w = tid >> 5;
    const int wm = (w & 3) * 32;       // 4 m-groups
    const int wn = (w >> 2) * 16;      // 4 n-groups of 16 cols

    float d[3][2][2][4];
    #pragma unroll
    for (int s = 0; s < 3; s++)
        #pragma unroll
        for (int mt = 0; mt < 2; mt++)
            #pragma unroll
            for (int nt = 0; nt < 2; nt++)
                #pragma unroll
                for (int q = 0; q < 4; q++) d[s][mt][nt][q] = 0.f;

    const uint32_t sbase = smem_u32(smh);
    const int t8 = lane >> 3, r8 = lane & 7;
    uint32_t aA[2];
    #pragma unroll
    for (int mt = 0; mt < 2; mt++) {
        int row = wm + mt * 16 + (t8 & 1) * 8 + r8;
        aA[mt] = sbase + (uint32_t)(row * PITCH + (t8 >> 1) * 8) * 2;
    }
    const uint32_t Bbase = sbase + 128 * PITCH * 2;
    uint32_t aB[3];
    #pragma unroll
    for (int s = 0; s < 3; s++) {
        int row = s * 64 + wn + (t8 >> 1) * 8 + r8;
        aB[s] = Bbase + (uint32_t)(row * PITCH + (t8 & 1) * 8) * 2;
    }

    #pragma unroll
    for (int kk = 0; kk < 8; kk++) {
        const uint32_t ko = kk * 32;
        uint32_t a[2][4];
        #pragma unroll
        for (int mt = 0; mt < 2; mt++) LDSM4(a[mt], aA[mt] + ko);
        #pragma unroll
        for (int s = 0; s < 3; s++) {
            uint32_t b[4];
            LDSM4(b, aB[s] + ko);
            #pragma unroll
            for (int mt = 0; mt < 2; mt++)
                #pragma unroll
                for (int nt = 0; nt < 2; nt++) {
                    int o = nt * 2;
                    MMA_FP16(d[s][mt][nt], a[mt], b[o], b[o + 1]);
                }
        }
    }

    const int rr = lane >> 2, c2 = (lane & 3) * 2;
    #pragma unroll
    for (int mt = 0; mt < 2; mt++)
        #pragma unroll
        for (int nt = 0; nt < 2; nt++) {
            int col = c0 + wn + nt * 8 + c2;
            float bhr0 = b_hh[col],       bhr1 = b_hh[col + 1];
            float bhz0 = b_hh[128 + col], bhz1 = b_hh[128 + col + 1];
            float bhn0 = b_hh[256 + col], bhn1 = b_hh[256 + col + 1];
            #pragma unroll
            for (int half = 0; half < 2; half++) {
                int row = m0 + wm + mt * 16 + rr + half * 8;
                if (row >= M) continue;
                size_t gb = (size_t)row * 384 + col;
                float2 gir = __half22float2(*(const __half2*)(gi + gb));
                float2 giz = __half22float2(*(const __half2*)(gi + gb + 128));
                float2 gin = __half22float2(*(const __half2*)(gi + gb + 256));
                float ghr0 = d[0][mt][nt][half * 2]     + bhr0;
                float ghr1 = d[0][mt][nt][half * 2 + 1] + bhr1;
                float ghz0 = d[1][mt][nt][half * 2]     + bhz0;
                float ghz1 = d[1][mt][nt][half * 2 + 1] + bhz1;
                float ghn0 = d[2][mt][nt][half * 2]     + bhn0;
                float ghn1 = d[2][mt][nt][half * 2 + 1] + bhn1;
                float r0 = 1.f / (1.f + __expf(-(gir.x + ghr0)));
                float r1 = 1.f / (1.f + __expf(-(gir.y + ghr1)));
                float z0 = 1.f / (1.f + __expf(-(giz.x + ghz0)));
                float z1 = 1.f / (1.f + __expf(-(giz.y + ghz1)));
                float n0v = tanhf(gin.x + r0 * ghn0);
                float n1v = tanhf(gin.y + r1 * ghn1);
                float2 hv = *(const float2*)(h + (size_t)row * H + col);
                float2 o;
                o.x = (1.f - z0) * n0v + z0 * hv.x;
                o.y = (1.f - z1) * n1v + z1 * hv.y;
                *(float2*)(out + (size_t)row * H + col) = o;
            }
        }
}

// ---------------- launch ----------------
static cudaStream_t s_prep = 0;
static cudaEvent_t  s_ev_fork = 0, s_ev_hw = 0, s_ev_agg = 0;
static cudaEvent_t  s_ev_gi1 = 0, s_ev_gi2 = 0, s_ev_done = 0;

extern "C" void kernel_launch(void* const* d_in, const int* in_sizes, int n_in,
                              void* d_out, int out_size) {
    const float* h     = (const float*)d_in[0];
    const int*   eidx  = (const int*)  d_in[1];
    const int*   etype = (const int*)  d_in[2];
    const float* W_msg = (const float*)d_in[4];
    const float* b_msg = (const float*)d_in[5];
    const float* emb   = (const float*)d_in[6];
    const float* W_ih  = (const float*)d_in[7];
    const float* W_hh  = (const float*)d_in[8];
    const float* b_ih  = (const float*)d_in[9];
    const float* b_hh  = (const float*)d_in[10];
    float* out = (float*)d_out;

    if (s_prep == 0) {
        cudaStreamCreateWithFlags(&s_prep, cudaStreamNonBlocking);
        cudaEventCreateWithFlags(&s_ev_fork, cudaEventDisableTiming);
        cudaEventCreateWithFlags(&s_ev_hw,   cudaEventDisableTiming);
        cudaEventCreateWithFlags(&s_ev_agg,  cudaEventDisableTiming);
        cudaEventCreateWithFlags(&s_ev_gi1,  cudaEventDisableTiming);
        cudaEventCreateWithFlags(&s_ev_gi2,  cudaEventDisableTiming);
        cudaEventCreateWithFlags(&s_ev_done, cudaEventDisableTiming);
    }

    __half *hWh, *gih, *mh, *wh;
    cudaGetSymbolAddress((void**)&hWh, g_hWh);
    cudaGetSymbolAddress((void**)&gih, g_gih);
    cudaGetSymbolAddress((void**)&mh,  g_mh);
    cudaGetSymbolAddress((void**)&wh,  g_wh);

    cudaFuncSetAttribute(mma_gemm<true>,  cudaFuncAttributeMaxDynamicSharedMemorySize, MMA_SMEM);
    cudaFuncSetAttribute(mma_gemm<false>, cudaFuncAttributeMaxDynamicSharedMemorySize, MMA_SMEM);
    cudaFuncSetAttribute(gh_gates_kernel, cudaFuncAttributeMaxDynamicSharedMemorySize, GGF_SMEM);

    const int W_IH_OFF = 128 * H;
    const int W_HH_OFF = (128 + 384) * H;

    // fork
    cudaEventRecord(s_ev_fork, 0);
    cudaStreamWaitEvent(s_prep, s_ev_fork, 0);

    // prep stream: CSR build (zero_deg removed: g_deg is self-cleaning)
    count_kernel  <<<(NEDGES + 255) / 256, 256, 0, s_prep>>>(eidx);
    scan1_kernel<<<NSB, SBLK, 0, s_prep>>>();
    scan3_kernel<<<NSB, SBLK, 0, s_prep>>>();
    scatter_kernel<<<(NEDGES + 255) / 256, 256, 0, s_prep>>>(eidx, etype);

    // main stream: weight convert -> hW GEMM (fp16 out)
    convert_w_kernel<<<((128 + 768) * 32 + 255) / 256, 256>>>(W_msg, W_ih, W_hh);
    mma_gemm<true><<<dim3(GB_TOT, 1), 256, MMA_SMEM>>>(h, nullptr, wh,
                                                       b_msg, hWh, NNODES, 128, 0);
    cudaEventRecord(s_ev_hw, 0);

    // prep stream: single aggregate (needs hW + CSR)
    cudaStreamWaitEvent(s_prep, s_ev_hw, 0);
    aggregate_kernel<<<(NNODES * 32 + 255) / 256, 256, 0, s_prep>>>(emb);
    cudaEventRecord(s_ev_agg, s_prep);

    // main stream: gi GEMM halves (fp16 out)
    cudaStreamWaitEvent(0, s_ev_agg, 0);
    mma_gemm<false><<<dim3(GB1, 3), 256, MMA_SMEM>>>(nullptr, mh, wh + W_IH_OFF,
                                                     b_ih, gih, NNODES, 384, 0);
    cudaEventRecord(s_ev_gi1, 0);
    mma_gemm<false><<<dim3(GB2, 3), 256, MMA_SMEM>>>(nullptr, mh, wh + W_IH_OFF,
                                                     b_ih, gih, NNODES, 384, GB1);
    cudaEventRecord(s_ev_gi2, 0);

    // prep stream: gh+gates halves, overlapping gi half2 on main
    cudaStreamWaitEvent(s_prep, s_ev_gi1, 0);
    gh_gates_kernel<<<dim3(GB1, 2), 512, GGF_SMEM, s_prep>>>(h, wh + W_HH_OFF,
                                                             b_hh, gih, out, NNODES, 0);
    cudaStreamWaitEvent(s_prep, s_ev_gi2, 0);
    gh_gates_kernel<<<dim3(GB2, 2), 512, GGF_SMEM, s_prep>>>(h, wh + W_HH_OFF,
                                                             b_hh, gih, out, NNODES, GB1);
    cudaEventRecord(s_ev_done, s_prep);

    // join back to origin stream for capture
    cudaStreamWaitEvent(0, s_ev_done, 0);
}